// round 6
// baseline (speedup 1.0000x reference)
#include <cuda_runtime.h>
#include <math.h>

#define NN 16384      // total nodes (B*N)
#define NB 4096       // nodes per batch
#define KNB 16        // kNN K

// ---------------- scratch ----------------
__device__ float g_xp[NN * 8];
__device__ int   g_nbr[NN * KNB];
__device__ float g_h[NN * 256];
__device__ float g_act0[NN * 256];
__device__ float g_act1[NN * 256];
__device__ float g_als[NN * 4];
__device__ float g_ald[NN * 4];

__device__ __forceinline__ float geluf(float v) {
    return 0.5f * v * (1.0f + erff(v * 0.7071067811865476f));
}

// ---------------- packed f32x2 helpers ----------------
__device__ __forceinline__ unsigned long long pk2(float lo, float hi) {
    unsigned long long r;
    asm("mov.b64 %0, {%1,%2};" : "=l"(r) : "f"(lo), "f"(hi));
    return r;
}
__device__ __forceinline__ void upk2(float& lo, float& hi, unsigned long long v) {
    asm("mov.b64 {%0,%1}, %2;" : "=f"(lo), "=f"(hi) : "l"(v));
}
__device__ __forceinline__ void fma2(unsigned long long& d, unsigned long long a,
                                     unsigned long long b) {
    asm("fma.rn.f32x2 %0, %1, %2, %0;" : "+l"(d) : "l"(a), "l"(b));
}

// ---------------- prep ----------------
__global__ void prep_kernel(const float* __restrict__ x, float* __restrict__ xp) {
    int i = blockIdx.x * blockDim.x + threadIdx.x;
    if (i >= NN) return;
    float s = 0.f;
    float v[6];
#pragma unroll
    for (int d = 0; d < 6; d++) { v[d] = x[i * 6 + d]; s += v[d] * v[d]; }
#pragma unroll
    for (int d = 0; d < 6; d++) xp[i * 8 + d] = v[d];
    xp[i * 8 + 6] = s;
    xp[i * 8 + 7] = 0.f;
}

// ---------------- zero helper ----------------
__global__ void zero2_kernel(float* __restrict__ a, float* __restrict__ b, int n) {
    int i = blockIdx.x * blockDim.x + threadIdx.x;
    if (i < n) { a[i] = 0.f; b[i] = 0.f; }
}

// ---------------- kNN ----------------
__global__ void knn_kernel(const float* __restrict__ xp, int* __restrict__ nbr) {
    int gwarp = (blockIdx.x * blockDim.x + threadIdx.x) >> 5;
    int lane = threadIdx.x & 31;
    if (gwarp >= NN) return;
    int q = gwarp;
    int base = q & ~(NB - 1);

    const float4* xp4 = (const float4*)xp;
    float4 q0 = xp4[(size_t)q * 2];
    float4 q1 = xp4[(size_t)q * 2 + 1];
    float sqq = q1.z;

    float s_d = 1e30f;
    int   s_i = -1;

    for (int j0 = 0; j0 < NB; j0 += 32) {
        int g = base + j0 + lane;
        float4 c0 = xp4[(size_t)g * 2];
        float4 c1 = xp4[(size_t)g * 2 + 1];
        float dot = q0.x * c0.x + q0.y * c0.y + q0.z * c0.z + q0.w * c0.w
                  + q1.x * c1.x + q1.y * c1.y;
        float d2 = sqq + c1.z - 2.0f * dot;
        if (g == q) d2 = 1e30f;

        float thresh = __shfl_sync(0xffffffffu, s_d, 15);
        unsigned ball = __ballot_sync(0xffffffffu, d2 < thresh);
        while (ball) {
            int src = __ffs(ball) - 1;
            ball &= ball - 1;
            float v  = __shfl_sync(0xffffffffu, d2, src);
            int   vi = base + j0 + src;
            float up_d = __shfl_up_sync(0xffffffffu, s_d, 1);
            int   up_i = __shfl_up_sync(0xffffffffu, s_i, 1);
            unsigned lt = __ballot_sync(0xffffffffu, s_d < v);
            int pos = __popc(lt);
            if (pos < 16) {
                if (lane == pos)      { s_d = v;    s_i = vi;   }
                else if (lane > pos)  { s_d = up_d; s_i = up_i; }
            }
        }
    }
    if (lane < 16) nbr[q * KNB + lane] = s_i;
}

// ---------------- layer-1 GEMM (K=6) + direct logits ----------------
__global__ void gemm6_kernel(const float* __restrict__ x, const float* __restrict__ W,
                             const float* __restrict__ a_s, const float* __restrict__ a_d,
                             float* __restrict__ h, float* __restrict__ als,
                             float* __restrict__ ald) {
    __shared__ float sW[6 * 256];
    __shared__ float sAs[256], sAd[256];
    int t = threadIdx.x;
    for (int i = t; i < 6 * 256; i += 256) sW[i] = W[i];
    sAs[t] = a_s[t]; sAd[t] = a_d[t];
    __syncthreads();

    int warp = t >> 5, lane = t & 31;
    int node = blockIdx.x * 8 + warp;
    float xr[6];
#pragma unroll
    for (int d = 0; d < 6; d++) xr[d] = x[node * 6 + d];
    int cbase = lane * 8;
    float out[8];
#pragma unroll
    for (int c = 0; c < 8; c++) {
        float s = 0.f;
#pragma unroll
        for (int d = 0; d < 6; d++) s += xr[d] * sW[d * 256 + cbase + c];
        out[c] = s;
    }
    *(float4*)&h[(size_t)node * 256 + cbase] = make_float4(out[0], out[1], out[2], out[3]);
    *(float4*)&h[(size_t)node * 256 + cbase + 4] = make_float4(out[4], out[5], out[6], out[7]);

    float ps = 0.f, pd = 0.f;
#pragma unroll
    for (int c = 0; c < 8; c++) {
        ps += out[c] * sAs[cbase + c];
        pd += out[c] * sAd[cbase + c];
    }
#pragma unroll
    for (int off = 1; off <= 4; off <<= 1) {
        ps += __shfl_xor_sync(0xffffffffu, ps, off);
        pd += __shfl_xor_sync(0xffffffffu, pd, off);
    }
    if ((lane & 7) == 0) {
        int hh = lane >> 3;
        als[node * 4 + hh] = ps;
        ald[node * 4 + hh] = pd;
    }
}

// ---------------- main GEMM: 128x64 tile, 8x4/thread, packed f32x2 FMA ----------
__global__ void gemm_tile_kernel(const float* __restrict__ A, const float* __restrict__ W,
                                 const float* __restrict__ bias, float* __restrict__ C,
                                 int K, int N, int actGelu,
                                 const float* __restrict__ a_s, const float* __restrict__ a_d,
                                 float* __restrict__ als, float* __restrict__ ald,
                                 int H, int headShift) {
    __shared__ float As[16][136];     // [k][row] (row-major pairs are adjacent)
    __shared__ float Ws2[16][128];    // [k][2*col] duplicated W values

    int t = threadIdx.x;
    int tx = t & 15;
    int ty = t >> 4;
    int row0 = blockIdx.x * 128;
    int c0 = blockIdx.y * 64;

    unsigned long long accp[4][4];    // [rowpair][col]: (C[2rp][c], C[2rp+1][c])
#pragma unroll
    for (int rp = 0; rp < 4; rp++)
#pragma unroll
        for (int c = 0; c < 4; c++) accp[rp][c] = 0ULL;

    float4 aReg[2], wReg;
    int aR[2], aKq[2];
#pragma unroll
    for (int i = 0; i < 2; i++) {
        int lin = t + i * 256;
        aR[i] = lin >> 2;
        aKq[i] = lin & 3;
    }
    int wK = t >> 4, wC = (t & 15) * 4;

#pragma unroll
    for (int i = 0; i < 2; i++)
        aReg[i] = *(const float4*)&A[(size_t)(row0 + aR[i]) * K + aKq[i] * 4];
    wReg = *(const float4*)&W[(size_t)wK * N + c0 + wC];

    int nchunks = K >> 4;
    for (int ch = 0; ch < nchunks; ch++) {
#pragma unroll
        for (int i = 0; i < 2; i++) {
            As[aKq[i] * 4 + 0][aR[i]] = aReg[i].x;
            As[aKq[i] * 4 + 1][aR[i]] = aReg[i].y;
            As[aKq[i] * 4 + 2][aR[i]] = aReg[i].z;
            As[aKq[i] * 4 + 3][aR[i]] = aReg[i].w;
        }
        *(float4*)&Ws2[wK][wC * 2]     = make_float4(wReg.x, wReg.x, wReg.y, wReg.y);
        *(float4*)&Ws2[wK][wC * 2 + 4] = make_float4(wReg.z, wReg.z, wReg.w, wReg.w);
        __syncthreads();

        if (ch + 1 < nchunks) {
            int k0 = (ch + 1) << 4;
#pragma unroll
            for (int i = 0; i < 2; i++)
                aReg[i] = *(const float4*)&A[(size_t)(row0 + aR[i]) * K + k0 + aKq[i] * 4];
            wReg = *(const float4*)&W[(size_t)(k0 + wK) * N + c0 + wC];
        }

#pragma unroll
        for (int k = 0; k < 16; k++) {
            ulonglong2 a01 = *(const ulonglong2*)&As[k][ty * 8];       // rows (0,1),(2,3)
            ulonglong2 a23 = *(const ulonglong2*)&As[k][ty * 8 + 4];   // rows (4,5),(6,7)
            ulonglong2 w01 = *(const ulonglong2*)&Ws2[k][tx * 8];      // (c0,c0),(c1,c1)
            ulonglong2 w23 = *(const ulonglong2*)&Ws2[k][tx * 8 + 4];  // (c2,c2),(c3,c3)
            fma2(accp[0][0], a01.x, w01.x); fma2(accp[0][1], a01.x, w01.y);
            fma2(accp[0][2], a01.x, w23.x); fma2(accp[0][3], a01.x, w23.y);
            fma2(accp[1][0], a01.y, w01.x); fma2(accp[1][1], a01.y, w01.y);
            fma2(accp[1][2], a01.y, w23.x); fma2(accp[1][3], a01.y, w23.y);
            fma2(accp[2][0], a23.x, w01.x); fma2(accp[2][1], a23.x, w01.y);
            fma2(accp[2][2], a23.x, w23.x); fma2(accp[2][3], a23.x, w23.y);
            fma2(accp[3][0], a23.y, w01.x); fma2(accp[3][1], a23.y, w01.y);
            fma2(accp[3][2], a23.y, w23.x); fma2(accp[3][3], a23.y, w23.y);
        }
        __syncthreads();
    }

    // unpack accumulators
    float acc[8][4];
#pragma unroll
    for (int rp = 0; rp < 4; rp++)
#pragma unroll
        for (int c = 0; c < 4; c++)
            upk2(acc[2 * rp][c], acc[2 * rp + 1][c], accp[rp][c]);

    if (als) {
        float4 asv = *(const float4*)&a_s[c0 + tx * 4];
        float4 adv = *(const float4*)&a_d[c0 + tx * 4];
        float ps[8], pd[8];
#pragma unroll
        for (int r = 0; r < 8; r++) {
            ps[r] = acc[r][0] * asv.x + acc[r][1] * asv.y + acc[r][2] * asv.z + acc[r][3] * asv.w;
            pd[r] = acc[r][0] * adv.x + acc[r][1] * adv.y + acc[r][2] * adv.z + acc[r][3] * adv.w;
        }
#pragma unroll
        for (int off = 1; off <= 8; off <<= 1) {
#pragma unroll
            for (int r = 0; r < 8; r++) {
                ps[r] += __shfl_xor_sync(0xffffffffu, ps[r], off);
                pd[r] += __shfl_xor_sync(0xffffffffu, pd[r], off);
            }
        }
        if (tx == 0) {
            int hb = c0 >> headShift;
#pragma unroll
            for (int r = 0; r < 8; r++) {
                atomicAdd(&als[(size_t)(row0 + ty * 8 + r) * H + hb], ps[r]);
                atomicAdd(&ald[(size_t)(row0 + ty * 8 + r) * H + hb], pd[r]);
            }
        }
    }

    float4 bb = make_float4(0.f, 0.f, 0.f, 0.f);
    if (bias) bb = *(const float4*)&bias[c0 + tx * 4];
#pragma unroll
    for (int r = 0; r < 8; r++) {
        float v0 = acc[r][0] + bb.x, v1 = acc[r][1] + bb.y,
              v2 = acc[r][2] + bb.z, v3 = acc[r][3] + bb.w;
        if (actGelu) { v0 = geluf(v0); v1 = geluf(v1); v2 = geluf(v2); v3 = geluf(v3); }
        *(float4*)&C[(size_t)(row0 + ty * 8 + r) * N + c0 + tx * 4] =
            make_float4(v0, v1, v2, v3);
    }
}

// ---------------- warp-per-node GAT aggregate (H=4, F=256), batched loads ---------
__global__ void __launch_bounds__(256) warp_agg4_kernel(
        const float* __restrict__ h, const int* __restrict__ nbr,
        const float* __restrict__ als, const float* __restrict__ ald,
        const float* __restrict__ bias, float* __restrict__ out) {
    __shared__ float s_alpha[8][68];
    int warp = threadIdx.x >> 5, lane = threadIdx.x & 31;
    int i = blockIdx.x * 8 + warp;

    int nbr_j = i;
    if (lane < 16) nbr_j = nbr[i * KNB + lane];

    float4 sv = *(const float4*)&als[nbr_j * 4];
    float4 dv = *(const float4*)&ald[i * 4];
    float e0 = sv.x + dv.x, e1 = sv.y + dv.y, e2 = sv.z + dv.z, e3 = sv.w + dv.w;
    e0 = e0 > 0.f ? e0 : 0.2f * e0;
    e1 = e1 > 0.f ? e1 : 0.2f * e1;
    e2 = e2 > 0.f ? e2 : 0.2f * e2;
    e3 = e3 > 0.f ? e3 : 0.2f * e3;
    float m0 = lane < 17 ? e0 : -1e30f, m1 = lane < 17 ? e1 : -1e30f;
    float m2 = lane < 17 ? e2 : -1e30f, m3 = lane < 17 ? e3 : -1e30f;
#pragma unroll
    for (int off = 16; off > 0; off >>= 1) {
        m0 = fmaxf(m0, __shfl_xor_sync(0xffffffffu, m0, off));
        m1 = fmaxf(m1, __shfl_xor_sync(0xffffffffu, m1, off));
        m2 = fmaxf(m2, __shfl_xor_sync(0xffffffffu, m2, off));
        m3 = fmaxf(m3, __shfl_xor_sync(0xffffffffu, m3, off));
    }
    float x0 = lane < 17 ? __expf(e0 - m0) : 0.f;
    float x1 = lane < 17 ? __expf(e1 - m1) : 0.f;
    float x2 = lane < 17 ? __expf(e2 - m2) : 0.f;
    float x3 = lane < 17 ? __expf(e3 - m3) : 0.f;
    float d0 = x0, d1 = x1, d2 = x2, d3 = x3;
#pragma unroll
    for (int off = 16; off > 0; off >>= 1) {
        d0 += __shfl_xor_sync(0xffffffffu, d0, off);
        d1 += __shfl_xor_sync(0xffffffffu, d1, off);
        d2 += __shfl_xor_sync(0xffffffffu, d2, off);
        d3 += __shfl_xor_sync(0xffffffffu, d3, off);
    }
    if (lane < 17) {
        s_alpha[warp][0 * 17 + lane] = x0 / d0;
        s_alpha[warp][1 * 17 + lane] = x1 / d1;
        s_alpha[warp][2 * 17 + lane] = x2 / d2;
        s_alpha[warp][3 * 17 + lane] = x3 / d3;
    }
    __syncwarp();

    int fbase = lane * 8;
    int hh = lane >> 3;
    unsigned long long acc[4] = {0ULL, 0ULL, 0ULL, 0ULL};

#pragma unroll
    for (int jb = 0; jb < 16; jb += 4) {
        ulonglong2 va[4], vb[4];
        unsigned long long ad[4];
#pragma unroll
        for (int b = 0; b < 4; b++) {
            int g = __shfl_sync(0xffffffffu, nbr_j, jb + b);
            float a = s_alpha[warp][hh * 17 + jb + b];
            ad[b] = pk2(a, a);
            const ulonglong2* p = (const ulonglong2*)(h + g * 256 + fbase);
            va[b] = p[0]; vb[b] = p[1];
        }
#pragma unroll
        for (int b = 0; b < 4; b++) {
            fma2(acc[0], ad[b], va[b].x);
            fma2(acc[1], ad[b], va[b].y);
            fma2(acc[2], ad[b], vb[b].x);
            fma2(acc[3], ad[b], vb[b].y);
        }
    }
    {   // self loop (j = 16)
        float a = s_alpha[warp][hh * 17 + 16];
        unsigned long long ad = pk2(a, a);
        const ulonglong2* p = (const ulonglong2*)(h + i * 256 + fbase);
        ulonglong2 va = p[0], vb = p[1];
        fma2(acc[0], ad, va.x);
        fma2(acc[1], ad, va.y);
        fma2(acc[2], ad, vb.x);
        fma2(acc[3], ad, vb.y);
    }

    float f[8];
    upk2(f[0], f[1], acc[0]); upk2(f[2], f[3], acc[1]);
    upk2(f[4], f[5], acc[2]); upk2(f[6], f[7], acc[3]);
    float4 b0 = *(const float4*)&bias[fbase];
    float4 b1 = *(const float4*)&bias[fbase + 4];
    float4 o0 = make_float4(geluf(f[0] + b0.x), geluf(f[1] + b0.y),
                            geluf(f[2] + b0.z), geluf(f[3] + b0.w));
    float4 o1 = make_float4(geluf(f[4] + b1.x), geluf(f[5] + b1.y),
                            geluf(f[6] + b1.z), geluf(f[7] + b1.w));
    *(float4*)&out[i * 256 + fbase] = o0;
    *(float4*)&out[i * 256 + fbase + 4] = o1;
}

// ---------------- warp-per-node GAT aggregate (H=1, F=128) + residual -------------
__global__ void __launch_bounds__(256) warp_agg1_kernel(
        const float* __restrict__ h, const int* __restrict__ nbr,
        const float* __restrict__ als, const float* __restrict__ ald,
        const float* __restrict__ bias, float* __restrict__ out,
        const float* __restrict__ x6, const float* __restrict__ resW,
        const float* __restrict__ resb) {
    int warp = threadIdx.x >> 5, lane = threadIdx.x & 31;
    int i = blockIdx.x * 8 + warp;

    int nbr_j = i;
    if (lane < 16) nbr_j = nbr[i * KNB + lane];

    float e = als[nbr_j] + ald[i];
    e = e > 0.f ? e : 0.2f * e;
    float m = lane < 17 ? e : -1e30f;
#pragma unroll
    for (int off = 16; off > 0; off >>= 1)
        m = fmaxf(m, __shfl_xor_sync(0xffffffffu, m, off));
    float xe = lane < 17 ? __expf(e - m) : 0.f;
    float den = xe;
#pragma unroll
    for (int off = 16; off > 0; off >>= 1)
        den += __shfl_xor_sync(0xffffffffu, den, off);
    float alpha = xe / den;

    int fbase = lane * 4;
    unsigned long long acc[2] = {0ULL, 0ULL};
#pragma unroll
    for (int jb = 0; jb < 16; jb += 4) {
        ulonglong2 v[4];
        unsigned long long ad[4];
#pragma unroll
        for (int b = 0; b < 4; b++) {
            int g = __shfl_sync(0xffffffffu, nbr_j, jb + b);
            float a = __shfl_sync(0xffffffffu, alpha, jb + b);
            ad[b] = pk2(a, a);
            v[b] = *(const ulonglong2*)(h + g * 128 + fbase);
        }
#pragma unroll
        for (int b = 0; b < 4; b++) {
            fma2(acc[0], ad[b], v[b].x);
            fma2(acc[1], ad[b], v[b].y);
        }
    }
    {   // self loop
        float a = __shfl_sync(0xffffffffu, alpha, 16);
        unsigned long long ad = pk2(a, a);
        ulonglong2 v = *(const ulonglong2*)(h + i * 128 + fbase);
        fma2(acc[0], ad, v.x);
        fma2(acc[1], ad, v.y);
    }

    float f[4];
    upk2(f[0], f[1], acc[0]); upk2(f[2], f[3], acc[1]);
    float4 bb = *(const float4*)&bias[fbase];
    float4 o = make_float4(geluf(f[0] + bb.x), geluf(f[1] + bb.y),
                           geluf(f[2] + bb.z), geluf(f[3] + bb.w));
    float4 r = *(const float4*)&resb[fbase];
#pragma unroll
    for (int d = 0; d < 6; d++) {
        float xv = x6[i * 6 + d];
        float4 w = *(const float4*)&resW[d * 128 + fbase];
        r.x += xv * w.x; r.y += xv * w.y; r.z += xv * w.z; r.w += xv * w.w;
    }
    o.x += r.x; o.y += r.y; o.z += r.z; o.w += r.w;
    *(float4*)&out[i * 128 + fbase] = o;
}

// ---------------- final ----------------
__global__ void final_kernel(const float* __restrict__ A, const float* __restrict__ W,
                             const float* __restrict__ b, float* __restrict__ out) {
    __shared__ float Ws[64 * 6];
    __shared__ float sb[6];
    int t = threadIdx.x;
    for (int k = t; k < 64 * 6; k += blockDim.x) Ws[k] = W[k];
    if (t < 6) sb[t] = b[t];
    __syncthreads();

    int i = blockIdx.x * blockDim.x + t;
    if (i >= NN) return;
    float acc[6];
#pragma unroll
    for (int o = 0; o < 6; o++) acc[o] = sb[o];
    const float4* Ar = (const float4*)(A + (size_t)i * 64);
#pragma unroll
    for (int k4 = 0; k4 < 16; k4++) {
        float4 v = Ar[k4];
        int k = k4 * 4;
#pragma unroll
        for (int o = 0; o < 6; o++) {
            acc[o] += v.x * Ws[(k + 0) * 6 + o];
            acc[o] += v.y * Ws[(k + 1) * 6 + o];
            acc[o] += v.z * Ws[(k + 2) * 6 + o];
            acc[o] += v.w * Ws[(k + 3) * 6 + o];
        }
    }
#pragma unroll
    for (int o = 0; o < 6; o++) out[(size_t)i * 6 + o] = acc[o];
}

// ---------------- launch ----------------
extern "C" void kernel_launch(void* const* d_in, const int* in_sizes, int n_in,
                              void* d_out, int out_size) {
    const float* x    = (const float*)d_in[0];
    const float* W1   = (const float*)d_in[1];
    const float* as1  = (const float*)d_in[2];
    const float* ad1  = (const float*)d_in[3];
    const float* b1   = (const float*)d_in[4];
    const float* W2   = (const float*)d_in[5];
    const float* as2  = (const float*)d_in[6];
    const float* ad2  = (const float*)d_in[7];
    const float* b2   = (const float*)d_in[8];
    const float* W3   = (const float*)d_in[9];
    const float* as3  = (const float*)d_in[10];
    const float* ad3  = (const float*)d_in[11];
    const float* b3   = (const float*)d_in[12];
    const float* resW = (const float*)d_in[13];
    const float* resb = (const float*)d_in[14];
    const float* m1W  = (const float*)d_in[15];
    const float* m1b  = (const float*)d_in[16];
    const float* m2W  = (const float*)d_in[17];
    const float* m2b  = (const float*)d_in[18];
    const float* m3W  = (const float*)d_in[19];
    const float* m3b  = (const float*)d_in[20];

    float *xp, *h, *a0, *a1, *als, *ald;
    int* nbr;
    cudaGetSymbolAddress((void**)&xp,  g_xp);
    cudaGetSymbolAddress((void**)&nbr, g_nbr);
    cudaGetSymbolAddress((void**)&h,   g_h);
    cudaGetSymbolAddress((void**)&a0,  g_act0);
    cudaGetSymbolAddress((void**)&a1,  g_act1);
    cudaGetSymbolAddress((void**)&als, g_als);
    cudaGetSymbolAddress((void**)&ald, g_ald);

    prep_kernel<<<NN / 256, 256>>>(x, xp);
    knn_kernel<<<NN / 8, 256>>>(xp, nbr);

    // GAT layer 1 (6 -> 256, H=4)
    gemm6_kernel<<<NN / 8, 256>>>(x, W1, as1, ad1, h, als, ald);
    warp_agg4_kernel<<<NN / 8, 256>>>(h, nbr, als, ald, b1, a0);

    // GAT layer 2 (256 -> 256, H=4)
    zero2_kernel<<<(NN * 4 + 255) / 256, 256>>>(als, ald, NN * 4);
    gemm_tile_kernel<<<dim3(NN / 128, 4), 256>>>(a0, W2, nullptr, h, 256, 256, 0,
                                                 as2, ad2, als, ald, 4, 6);
    warp_agg4_kernel<<<NN / 8, 256>>>(h, nbr, als, ald, b2, a1);

    // GAT layer 3 (256 -> 128, H=1) + fused residual
    zero2_kernel<<<(NN + 255) / 256, 256>>>(als, ald, NN);
    gemm_tile_kernel<<<dim3(NN / 128, 2), 256>>>(a1, W3, nullptr, h, 256, 128, 0,
                                                 as3, ad3, als, ald, 1, 7);
    warp_agg1_kernel<<<NN / 8, 256>>>(h, nbr, als, ald, b3, a0, x, resW, resb);

    // MLP
    gemm_tile_kernel<<<dim3(NN / 128, 2), 256>>>(a0, m1W, m1b, a1, 128, 128, 1,
                                                 nullptr, nullptr, nullptr, nullptr, 0, 0);
    gemm_tile_kernel<<<dim3(NN / 128, 1), 256>>>(a1, m2W, m2b, h, 128, 64, 1,
                                                 nullptr, nullptr, nullptr, nullptr, 0, 0);
    final_kernel<<<NN / 128, 128>>>(h, m3W, m3b, (float*)d_out);
}

// round 7
// speedup vs baseline: 1.2326x; 1.2326x over previous
#include <cuda_runtime.h>
#include <math.h>

#define NN 16384      // total nodes (B*N)
#define NB 4096       // nodes per batch
#define KNB 16        // kNN K

// ---------------- scratch ----------------
__device__ float g_xp[NN * 8];
__device__ int   g_nbr[NN * KNB];
__device__ float g_h[NN * 256];
__device__ float g_act0[NN * 256];
__device__ float g_act1[NN * 256];
__device__ float g_als[NN * 4];
__device__ float g_ald[NN * 4];

__device__ __forceinline__ float geluf(float v) {
    return 0.5f * v * (1.0f + erff(v * 0.7071067811865476f));
}

// ---------------- prep ----------------
__global__ void prep_kernel(const float* __restrict__ x, float* __restrict__ xp) {
    int i = blockIdx.x * blockDim.x + threadIdx.x;
    if (i >= NN) return;
    float s = 0.f;
    float v[6];
#pragma unroll
    for (int d = 0; d < 6; d++) { v[d] = x[i * 6 + d]; s += v[d] * v[d]; }
#pragma unroll
    for (int d = 0; d < 6; d++) xp[i * 8 + d] = v[d];
    xp[i * 8 + 6] = s;
    xp[i * 8 + 7] = 0.f;
}

// ---------------- kNN ----------------
__global__ void knn_kernel(const float* __restrict__ xp, int* __restrict__ nbr) {
    int gwarp = (blockIdx.x * blockDim.x + threadIdx.x) >> 5;
    int lane = threadIdx.x & 31;
    if (gwarp >= NN) return;
    int q = gwarp;
    int base = q & ~(NB - 1);

    const float4* xp4 = (const float4*)xp;
    float4 q0 = xp4[(size_t)q * 2];
    float4 q1 = xp4[(size_t)q * 2 + 1];
    float sqq = q1.z;

    float s_d = 1e30f;
    int   s_i = -1;

    for (int j0 = 0; j0 < NB; j0 += 32) {
        int g = base + j0 + lane;
        float4 c0 = xp4[(size_t)g * 2];
        float4 c1 = xp4[(size_t)g * 2 + 1];
        float dot = q0.x * c0.x + q0.y * c0.y + q0.z * c0.z + q0.w * c0.w
                  + q1.x * c1.x + q1.y * c1.y;
        float d2 = sqq + c1.z - 2.0f * dot;
        if (g == q) d2 = 1e30f;

        float thresh = __shfl_sync(0xffffffffu, s_d, 15);
        unsigned ball = __ballot_sync(0xffffffffu, d2 < thresh);
        while (ball) {
            int src = __ffs(ball) - 1;
            ball &= ball - 1;
            float v  = __shfl_sync(0xffffffffu, d2, src);
            int   vi = base + j0 + src;
            float up_d = __shfl_up_sync(0xffffffffu, s_d, 1);
            int   up_i = __shfl_up_sync(0xffffffffu, s_i, 1);
            unsigned lt = __ballot_sync(0xffffffffu, s_d < v);
            int pos = __popc(lt);
            if (pos < 16) {
                if (lane == pos)      { s_d = v;    s_i = vi;   }
                else if (lane > pos)  { s_d = up_d; s_i = up_i; }
            }
        }
    }
    if (lane < 16) nbr[q * KNB + lane] = s_i;
}

// ---------------- layer-1 GEMM (K=6) + direct logits ----------------
__global__ void gemm6_kernel(const float* __restrict__ x, const float* __restrict__ W,
                             const float* __restrict__ a_s, const float* __restrict__ a_d,
                             float* __restrict__ h, float* __restrict__ als,
                             float* __restrict__ ald) {
    __shared__ float sW[6 * 256];
    __shared__ float sAs[256], sAd[256];
    int t = threadIdx.x;
    for (int i = t; i < 6 * 256; i += 256) sW[i] = W[i];
    sAs[t] = a_s[t]; sAd[t] = a_d[t];
    __syncthreads();

    int warp = t >> 5, lane = t & 31;
    int node = blockIdx.x * 8 + warp;
    float xr[6];
#pragma unroll
    for (int d = 0; d < 6; d++) xr[d] = x[node * 6 + d];
    int cbase = lane * 8;
    float out[8];
#pragma unroll
    for (int c = 0; c < 8; c++) {
        float s = 0.f;
#pragma unroll
        for (int d = 0; d < 6; d++) s += xr[d] * sW[d * 256 + cbase + c];
        out[c] = s;
    }
    *(float4*)&h[(size_t)node * 256 + cbase] = make_float4(out[0], out[1], out[2], out[3]);
    *(float4*)&h[(size_t)node * 256 + cbase + 4] = make_float4(out[4], out[5], out[6], out[7]);

    float ps = 0.f, pd = 0.f;
#pragma unroll
    for (int c = 0; c < 8; c++) {
        ps += out[c] * sAs[cbase + c];
        pd += out[c] * sAd[cbase + c];
    }
#pragma unroll
    for (int off = 1; off <= 4; off <<= 1) {
        ps += __shfl_xor_sync(0xffffffffu, ps, off);
        pd += __shfl_xor_sync(0xffffffffu, pd, off);
    }
    if ((lane & 7) == 0) {
        int hh = lane >> 3;
        als[node * 4 + hh] = ps;
        ald[node * 4 + hh] = pd;
    }
}

// ---------------- big GEMM: 128x128 tile, 8x8/thread, prefetch, fused logits -----
// C[M,N_cols_of_this_call] with N = row stride of W/C. Column tile = 128.
// Fused logits (if als): head = (c0 + tx*8) >> 6 (H=4) or single head (H=1);
// heads never span a 128-col block, reduction completes in-block -> plain store.
__global__ void __launch_bounds__(256) gemm128_kernel(
        const float* __restrict__ A, const float* __restrict__ W,
        const float* __restrict__ bias, float* __restrict__ C,
        int K, int N, int actGelu,
        const float* __restrict__ a_s, const float* __restrict__ a_d,
        float* __restrict__ als, float* __restrict__ ald, int H) {
    __shared__ float As[8][132];
    __shared__ float Ws[8][128];

    int t = threadIdx.x;
    int tx = t & 15;
    int ty = t >> 4;
    int row0 = blockIdx.x * 128;
    int c0 = blockIdx.y * 128;

    float acc[8][8];
#pragma unroll
    for (int r = 0; r < 8; r++)
#pragma unroll
        for (int c = 0; c < 8; c++) acc[r][c] = 0.f;

    int aRow = t >> 1, aK = (t & 1) * 4;
    int wK = t >> 5, wC = (t & 31) * 4;

    float4 aReg = *(const float4*)&A[(size_t)(row0 + aRow) * K + aK];
    float4 wReg = *(const float4*)&W[(size_t)wK * N + c0 + wC];

    int nch = K >> 3;
    for (int ch = 0; ch < nch; ch++) {
        As[aK + 0][aRow] = aReg.x;
        As[aK + 1][aRow] = aReg.y;
        As[aK + 2][aRow] = aReg.z;
        As[aK + 3][aRow] = aReg.w;
        *(float4*)&Ws[wK][wC] = wReg;
        __syncthreads();

        if (ch + 1 < nch) {
            int k0 = (ch + 1) << 3;
            aReg = *(const float4*)&A[(size_t)(row0 + aRow) * K + k0 + aK];
            wReg = *(const float4*)&W[(size_t)(k0 + wK) * N + c0 + wC];
        }

#pragma unroll
        for (int k = 0; k < 8; k++) {
            float4 a0 = *(const float4*)&As[k][ty * 8];
            float4 a1 = *(const float4*)&As[k][ty * 8 + 4];
            float4 w0 = *(const float4*)&Ws[k][tx * 8];
            float4 w1 = *(const float4*)&Ws[k][tx * 8 + 4];
            float av[8] = {a0.x, a0.y, a0.z, a0.w, a1.x, a1.y, a1.z, a1.w};
            float wv[8] = {w0.x, w0.y, w0.z, w0.w, w1.x, w1.y, w1.z, w1.w};
#pragma unroll
            for (int r = 0; r < 8; r++)
#pragma unroll
                for (int c = 0; c < 8; c++)
                    acc[r][c] += av[r] * wv[c];
        }
        __syncthreads();
    }

    if (als) {
        float asv[8], adv[8];
#pragma unroll
        for (int j = 0; j < 8; j++) {
            asv[j] = a_s[c0 + tx * 8 + j];
            adv[j] = a_d[c0 + tx * 8 + j];
        }
        float ps[8], pd[8];
#pragma unroll
        for (int r = 0; r < 8; r++) {
            float s = 0.f, d = 0.f;
#pragma unroll
            for (int j = 0; j < 8; j++) { s += acc[r][j] * asv[j]; d += acc[r][j] * adv[j]; }
            ps[r] = s; pd[r] = d;
        }
#pragma unroll
        for (int off = 1; off <= 4; off <<= 1) {
#pragma unroll
            for (int r = 0; r < 8; r++) {
                ps[r] += __shfl_xor_sync(0xffffffffu, ps[r], off);
                pd[r] += __shfl_xor_sync(0xffffffffu, pd[r], off);
            }
        }
        if (H == 1) {
#pragma unroll
            for (int r = 0; r < 8; r++) {
                ps[r] += __shfl_xor_sync(0xffffffffu, ps[r], 8);
                pd[r] += __shfl_xor_sync(0xffffffffu, pd[r], 8);
            }
            if (tx == 0) {
#pragma unroll
                for (int r = 0; r < 8; r++) {
                    int row = row0 + ty * 8 + r;
                    als[row] = ps[r];
                    ald[row] = pd[r];
                }
            }
        } else {                 // H == 4, head fully inside 8-tx group
            if ((tx & 7) == 0) {
                int hb = (c0 + tx * 8) >> 6;
#pragma unroll
                for (int r = 0; r < 8; r++) {
                    int row = row0 + ty * 8 + r;
                    als[row * 4 + hb] = ps[r];
                    ald[row * 4 + hb] = pd[r];
                }
            }
        }
    }

    float bb[8] = {0.f, 0.f, 0.f, 0.f, 0.f, 0.f, 0.f, 0.f};
    if (bias) {
#pragma unroll
        for (int j = 0; j < 8; j++) bb[j] = bias[c0 + tx * 8 + j];
    }
#pragma unroll
    for (int r = 0; r < 8; r++) {
        float v[8];
#pragma unroll
        for (int j = 0; j < 8; j++) {
            v[j] = acc[r][j] + bb[j];
            if (actGelu) v[j] = geluf(v[j]);
        }
        float* dst = &C[(size_t)(row0 + ty * 8 + r) * N + c0 + tx * 8];
        *(float4*)dst = make_float4(v[0], v[1], v[2], v[3]);
        *(float4*)(dst + 4) = make_float4(v[4], v[5], v[6], v[7]);
    }
}

// ---------------- 128x64 GEMM (for N=64 MLP layer), plain FFMA ----------------
__global__ void gemm_tile_kernel(const float* __restrict__ A, const float* __restrict__ W,
                                 const float* __restrict__ bias, float* __restrict__ C,
                                 int K, int N, int actGelu) {
    __shared__ float As[16][136];
    __shared__ float Ws[16][64];

    int t = threadIdx.x;
    int tx = t & 15;
    int ty = t >> 4;
    int row0 = blockIdx.x * 128;
    int c0 = blockIdx.y * 64;

    float acc[8][4];
#pragma unroll
    for (int r = 0; r < 8; r++)
#pragma unroll
        for (int c = 0; c < 4; c++) acc[r][c] = 0.f;

    float4 aReg[2], wReg;
    int aR[2], aKq[2];
#pragma unroll
    for (int i = 0; i < 2; i++) {
        int lin = t + i * 256;
        aR[i] = lin >> 2;
        aKq[i] = lin & 3;
    }
    int wK = t >> 4, wC = (t & 15) * 4;

#pragma unroll
    for (int i = 0; i < 2; i++)
        aReg[i] = *(const float4*)&A[(size_t)(row0 + aR[i]) * K + aKq[i] * 4];
    wReg = *(const float4*)&W[(size_t)wK * N + c0 + wC];

    int nchunks = K >> 4;
    for (int ch = 0; ch < nchunks; ch++) {
#pragma unroll
        for (int i = 0; i < 2; i++) {
            As[aKq[i] * 4 + 0][aR[i]] = aReg[i].x;
            As[aKq[i] * 4 + 1][aR[i]] = aReg[i].y;
            As[aKq[i] * 4 + 2][aR[i]] = aReg[i].z;
            As[aKq[i] * 4 + 3][aR[i]] = aReg[i].w;
        }
        *(float4*)&Ws[wK][wC] = wReg;
        __syncthreads();

        if (ch + 1 < nchunks) {
            int k0 = (ch + 1) << 4;
#pragma unroll
            for (int i = 0; i < 2; i++)
                aReg[i] = *(const float4*)&A[(size_t)(row0 + aR[i]) * K + k0 + aKq[i] * 4];
            wReg = *(const float4*)&W[(size_t)(k0 + wK) * N + c0 + wC];
        }

#pragma unroll
        for (int k = 0; k < 16; k++) {
            float4 a0 = *(const float4*)&As[k][ty * 8];
            float4 a1 = *(const float4*)&As[k][ty * 8 + 4];
            float4 wv = *(const float4*)&Ws[k][tx * 4];
            acc[0][0] += a0.x * wv.x; acc[0][1] += a0.x * wv.y; acc[0][2] += a0.x * wv.z; acc[0][3] += a0.x * wv.w;
            acc[1][0] += a0.y * wv.x; acc[1][1] += a0.y * wv.y; acc[1][2] += a0.y * wv.z; acc[1][3] += a0.y * wv.w;
            acc[2][0] += a0.z * wv.x; acc[2][1] += a0.z * wv.y; acc[2][2] += a0.z * wv.z; acc[2][3] += a0.z * wv.w;
            acc[3][0] += a0.w * wv.x; acc[3][1] += a0.w * wv.y; acc[3][2] += a0.w * wv.z; acc[3][3] += a0.w * wv.w;
            acc[4][0] += a1.x * wv.x; acc[4][1] += a1.x * wv.y; acc[4][2] += a1.x * wv.z; acc[4][3] += a1.x * wv.w;
            acc[5][0] += a1.y * wv.x; acc[5][1] += a1.y * wv.y; acc[5][2] += a1.y * wv.z; acc[5][3] += a1.y * wv.w;
            acc[6][0] += a1.z * wv.x; acc[6][1] += a1.z * wv.y; acc[6][2] += a1.z * wv.z; acc[6][3] += a1.z * wv.w;
            acc[7][0] += a1.w * wv.x; acc[7][1] += a1.w * wv.y; acc[7][2] += a1.w * wv.z; acc[7][3] += a1.w * wv.w;
        }
        __syncthreads();
    }

    float4 bb = make_float4(0.f, 0.f, 0.f, 0.f);
    if (bias) bb = *(const float4*)&bias[c0 + tx * 4];
#pragma unroll
    for (int r = 0; r < 8; r++) {
        float v0 = acc[r][0] + bb.x, v1 = acc[r][1] + bb.y,
              v2 = acc[r][2] + bb.z, v3 = acc[r][3] + bb.w;
        if (actGelu) { v0 = geluf(v0); v1 = geluf(v1); v2 = geluf(v2); v3 = geluf(v3); }
        *(float4*)&C[(size_t)(row0 + ty * 8 + r) * N + c0 + tx * 4] =
            make_float4(v0, v1, v2, v3);
    }
}

// ---------------- warp-per-node GAT aggregate (H=4, F=256) ----------------
__global__ void warp_agg4_kernel(const float* __restrict__ h, const int* __restrict__ nbr,
                                 const float* __restrict__ als, const float* __restrict__ ald,
                                 const float* __restrict__ bias, float* __restrict__ out) {
    __shared__ float s_alpha[8][68];
    int warp = threadIdx.x >> 5, lane = threadIdx.x & 31;
    int i = blockIdx.x * 8 + warp;

    int nbr_j = i;
    if (lane < 16) nbr_j = nbr[i * KNB + lane];

    float4 sv = *(const float4*)&als[nbr_j * 4];
    float4 dv = *(const float4*)&ald[i * 4];
    float e0 = sv.x + dv.x, e1 = sv.y + dv.y, e2 = sv.z + dv.z, e3 = sv.w + dv.w;
    e0 = e0 > 0.f ? e0 : 0.2f * e0;
    e1 = e1 > 0.f ? e1 : 0.2f * e1;
    e2 = e2 > 0.f ? e2 : 0.2f * e2;
    e3 = e3 > 0.f ? e3 : 0.2f * e3;
    float m0 = lane < 17 ? e0 : -1e30f, m1 = lane < 17 ? e1 : -1e30f;
    float m2 = lane < 17 ? e2 : -1e30f, m3 = lane < 17 ? e3 : -1e30f;
#pragma unroll
    for (int off = 16; off > 0; off >>= 1) {
        m0 = fmaxf(m0, __shfl_xor_sync(0xffffffffu, m0, off));
        m1 = fmaxf(m1, __shfl_xor_sync(0xffffffffu, m1, off));
        m2 = fmaxf(m2, __shfl_xor_sync(0xffffffffu, m2, off));
        m3 = fmaxf(m3, __shfl_xor_sync(0xffffffffu, m3, off));
    }
    float x0 = lane < 17 ? __expf(e0 - m0) : 0.f;
    float x1 = lane < 17 ? __expf(e1 - m1) : 0.f;
    float x2 = lane < 17 ? __expf(e2 - m2) : 0.f;
    float x3 = lane < 17 ? __expf(e3 - m3) : 0.f;
    float d0 = x0, d1 = x1, d2 = x2, d3 = x3;
#pragma unroll
    for (int off = 16; off > 0; off >>= 1) {
        d0 += __shfl_xor_sync(0xffffffffu, d0, off);
        d1 += __shfl_xor_sync(0xffffffffu, d1, off);
        d2 += __shfl_xor_sync(0xffffffffu, d2, off);
        d3 += __shfl_xor_sync(0xffffffffu, d3, off);
    }
    if (lane < 17) {
        s_alpha[warp][0 * 17 + lane] = x0 / d0;
        s_alpha[warp][1 * 17 + lane] = x1 / d1;
        s_alpha[warp][2 * 17 + lane] = x2 / d2;
        s_alpha[warp][3 * 17 + lane] = x3 / d3;
    }
    __syncwarp();

    int fbase = lane * 8;
    int hh = lane >> 3;
    float4 acc0 = make_float4(0.f, 0.f, 0.f, 0.f);
    float4 acc1 = make_float4(0.f, 0.f, 0.f, 0.f);
#pragma unroll
    for (int j = 0; j < 17; j++) {
        int g = __shfl_sync(0xffffffffu, nbr_j, j);
        float a = s_alpha[warp][hh * 17 + j];
        const float4* p = (const float4*)(h + g * 256 + fbase);
        float4 v0 = p[0], v1 = p[1];
        acc0.x += a * v0.x; acc0.y += a * v0.y; acc0.z += a * v0.z; acc0.w += a * v0.w;
        acc1.x += a * v1.x; acc1.y += a * v1.y; acc1.z += a * v1.z; acc1.w += a * v1.w;
    }
    float4 b0 = *(const float4*)&bias[fbase];
    float4 b1 = *(const float4*)&bias[fbase + 4];
    float4 o0 = make_float4(geluf(acc0.x + b0.x), geluf(acc0.y + b0.y),
                            geluf(acc0.z + b0.z), geluf(acc0.w + b0.w));
    float4 o1 = make_float4(geluf(acc1.x + b1.x), geluf(acc1.y + b1.y),
                            geluf(acc1.z + b1.z), geluf(acc1.w + b1.w));
    *(float4*)&out[i * 256 + fbase] = o0;
    *(float4*)&out[i * 256 + fbase + 4] = o1;
}

// ---------------- warp-per-node GAT aggregate (H=1, F=128) + residual -------------
__global__ void warp_agg1_kernel(const float* __restrict__ h, const int* __restrict__ nbr,
                                 const float* __restrict__ als, const float* __restrict__ ald,
                                 const float* __restrict__ bias, float* __restrict__ out,
                                 const float* __restrict__ x6, const float* __restrict__ resW,
                                 const float* __restrict__ resb) {
    int warp = threadIdx.x >> 5, lane = threadIdx.x & 31;
    int i = blockIdx.x * 8 + warp;

    int nbr_j = i;
    if (lane < 16) nbr_j = nbr[i * KNB + lane];

    float e = als[nbr_j] + ald[i];
    e = e > 0.f ? e : 0.2f * e;
    float m = lane < 17 ? e : -1e30f;
#pragma unroll
    for (int off = 16; off > 0; off >>= 1)
        m = fmaxf(m, __shfl_xor_sync(0xffffffffu, m, off));
    float xe = lane < 17 ? __expf(e - m) : 0.f;
    float den = xe;
#pragma unroll
    for (int off = 16; off > 0; off >>= 1)
        den += __shfl_xor_sync(0xffffffffu, den, off);
    float alpha = xe / den;

    int fbase = lane * 4;
    float4 acc = make_float4(0.f, 0.f, 0.f, 0.f);
#pragma unroll
    for (int j = 0; j < 17; j++) {
        int g = __shfl_sync(0xffffffffu, nbr_j, j);
        float a = __shfl_sync(0xffffffffu, alpha, j);
        float4 v = *(const float4*)(h + g * 128 + fbase);
        acc.x += a * v.x; acc.y += a * v.y; acc.z += a * v.z; acc.w += a * v.w;
    }
    float4 bb = *(const float4*)&bias[fbase];
    float4 o = make_float4(geluf(acc.x + bb.x), geluf(acc.y + bb.y),
                           geluf(acc.z + bb.z), geluf(acc.w + bb.w));
    float4 r = *(const float4*)&resb[fbase];
#pragma unroll
    for (int d = 0; d < 6; d++) {
        float xv = x6[i * 6 + d];
        float4 w = *(const float4*)&resW[d * 128 + fbase];
        r.x += xv * w.x; r.y += xv * w.y; r.z += xv * w.z; r.w += xv * w.w;
    }
    o.x += r.x; o.y += r.y; o.z += r.z; o.w += r.w;
    *(float4*)&out[i * 128 + fbase] = o;
}

// ---------------- final ----------------
__global__ void final_kernel(const float* __restrict__ A, const float* __restrict__ W,
                             const float* __restrict__ b, float* __restrict__ out) {
    __shared__ float Ws[64 * 6];
    __shared__ float sb[6];
    int t = threadIdx.x;
    for (int k = t; k < 64 * 6; k += blockDim.x) Ws[k] = W[k];
    if (t < 6) sb[t] = b[t];
    __syncthreads();

    int i = blockIdx.x * blockDim.x + t;
    if (i >= NN) return;
    float acc[6];
#pragma unroll
    for (int o = 0; o < 6; o++) acc[o] = sb[o];
    const float4* Ar = (const float4*)(A + (size_t)i * 64);
#pragma unroll
    for (int k4 = 0; k4 < 16; k4++) {
        float4 v = Ar[k4];
        int k = k4 * 4;
#pragma unroll
        for (int o = 0; o < 6; o++) {
            acc[o] += v.x * Ws[(k + 0) * 6 + o];
            acc[o] += v.y * Ws[(k + 1) * 6 + o];
            acc[o] += v.z * Ws[(k + 2) * 6 + o];
            acc[o] += v.w * Ws[(k + 3) * 6 + o];
        }
    }
#pragma unroll
    for (int o = 0; o < 6; o++) out[(size_t)i * 6 + o] = acc[o];
}

// ---------------- launch ----------------
extern "C" void kernel_launch(void* const* d_in, const int* in_sizes, int n_in,
                              void* d_out, int out_size) {
    const float* x    = (const float*)d_in[0];
    const float* W1   = (const float*)d_in[1];
    const float* as1  = (const float*)d_in[2];
    const float* ad1  = (const float*)d_in[3];
    const float* b1   = (const float*)d_in[4];
    const float* W2   = (const float*)d_in[5];
    const float* as2  = (const float*)d_in[6];
    const float* ad2  = (const float*)d_in[7];
    const float* b2   = (const float*)d_in[8];
    const float* W3   = (const float*)d_in[9];
    const float* as3  = (const float*)d_in[10];
    const float* ad3  = (const float*)d_in[11];
    const float* b3   = (const float*)d_in[12];
    const float* resW = (const float*)d_in[13];
    const float* resb = (const float*)d_in[14];
    const float* m1W  = (const float*)d_in[15];
    const float* m1b  = (const float*)d_in[16];
    const float* m2W  = (const float*)d_in[17];
    const float* m2b  = (const float*)d_in[18];
    const float* m3W  = (const float*)d_in[19];
    const float* m3b  = (const float*)d_in[20];

    float *xp, *h, *a0, *a1, *als, *ald;
    int* nbr;
    cudaGetSymbolAddress((void**)&xp,  g_xp);
    cudaGetSymbolAddress((void**)&nbr, g_nbr);
    cudaGetSymbolAddress((void**)&h,   g_h);
    cudaGetSymbolAddress((void**)&a0,  g_act0);
    cudaGetSymbolAddress((void**)&a1,  g_act1);
    cudaGetSymbolAddress((void**)&als, g_als);
    cudaGetSymbolAddress((void**)&ald, g_ald);

    prep_kernel<<<NN / 256, 256>>>(x, xp);
    knn_kernel<<<NN / 8, 256>>>(xp, nbr);

    // GAT layer 1 (6 -> 256, H=4)
    gemm6_kernel<<<NN / 8, 256>>>(x, W1, as1, ad1, h, als, ald);
    warp_agg4_kernel<<<NN / 8, 256>>>(h, nbr, als, ald, b1, a0);

    // GAT layer 2 (256 -> 256, H=4): fused logits, complete in-block (no atomics)
    gemm128_kernel<<<dim3(NN / 128, 2), 256>>>(a0, W2, nullptr, h, 256, 256, 0,
                                               as2, ad2, als, ald, 4);
    warp_agg4_kernel<<<NN / 8, 256>>>(h, nbr, als, ald, b2, a1);

    // GAT layer 3 (256 -> 128, H=1) + fused residual
    gemm128_kernel<<<dim3(NN / 128, 1), 256>>>(a1, W3, nullptr, h, 256, 128, 0,
                                               as3, ad3, als, ald, 1);
    warp_agg1_kernel<<<NN / 8, 256>>>(h, nbr, als, ald, b3, a0, x, resW, resb);

    // MLP
    gemm128_kernel<<<dim3(NN / 128, 1), 256>>>(a0, m1W, m1b, a1, 128, 128, 1,
                                               nullptr, nullptr, nullptr, nullptr, 0);
    gemm_tile_kernel<<<dim3(NN / 128, 1), 256>>>(a1, m2W, m2b, h, 128, 64, 1);
    final_kernel<<<NN / 128, 128>>>(h, m3W, m3b, (float*)d_out);
}

// round 8
// speedup vs baseline: 1.4919x; 1.2104x over previous
#include <cuda_runtime.h>
#include <math.h>

#define NN 16384      // total nodes (B*N)
#define NB 4096       // nodes per batch
#define KNB 16        // kNN K

// ---------------- scratch ----------------
__device__ float g_xp[NN * 8];
__device__ int   g_nbr[NN * KNB];
__device__ float g_h[NN * 256];
__device__ float g_act0[NN * 256];
__device__ float g_act1[NN * 256];
__device__ float g_als[NN * 4];
__device__ float g_ald[NN * 4];

__device__ __forceinline__ float geluf(float v) {
    return 0.5f * v * (1.0f + erff(v * 0.7071067811865476f));
}

// fp32 -> tf32 (RNA rounding), bit pattern returned as float
__device__ __forceinline__ float cvt_tf32(float x) {
    unsigned r;
    asm("cvt.rna.tf32.f32 %0, %1;" : "=r"(r) : "f"(x));
    return __uint_as_float(r);
}

// one m16n8k8 tf32 MMA, D += A*B
__device__ __forceinline__ void mma8(float* d, const unsigned* a, const unsigned* b) {
    asm volatile(
        "mma.sync.aligned.m16n8k8.row.col.f32.tf32.tf32.f32 "
        "{%0,%1,%2,%3}, {%4,%5,%6,%7}, {%8,%9}, {%0,%1,%2,%3};"
        : "+f"(d[0]), "+f"(d[1]), "+f"(d[2]), "+f"(d[3])
        : "r"(a[0]), "r"(a[1]), "r"(a[2]), "r"(a[3]), "r"(b[0]), "r"(b[1]));
}

// ---------------- prep ----------------
__global__ void prep_kernel(const float* __restrict__ x, float* __restrict__ xp) {
    int i = blockIdx.x * blockDim.x + threadIdx.x;
    if (i >= NN) return;
    float s = 0.f;
    float v[6];
#pragma unroll
    for (int d = 0; d < 6; d++) { v[d] = x[i * 6 + d]; s += v[d] * v[d]; }
#pragma unroll
    for (int d = 0; d < 6; d++) xp[i * 8 + d] = v[d];
    xp[i * 8 + 6] = s;
    xp[i * 8 + 7] = 0.f;
}

// ---------------- kNN ----------------
__global__ void knn_kernel(const float* __restrict__ xp, int* __restrict__ nbr) {
    int gwarp = (blockIdx.x * blockDim.x + threadIdx.x) >> 5;
    int lane = threadIdx.x & 31;
    if (gwarp >= NN) return;
    int q = gwarp;
    int base = q & ~(NB - 1);

    const float4* xp4 = (const float4*)xp;
    float4 q0 = xp4[(size_t)q * 2];
    float4 q1 = xp4[(size_t)q * 2 + 1];
    float sqq = q1.z;

    float s_d = 1e30f;
    int   s_i = -1;

    for (int j0 = 0; j0 < NB; j0 += 32) {
        int g = base + j0 + lane;
        float4 c0 = xp4[(size_t)g * 2];
        float4 c1 = xp4[(size_t)g * 2 + 1];
        float dot = q0.x * c0.x + q0.y * c0.y + q0.z * c0.z + q0.w * c0.w
                  + q1.x * c1.x + q1.y * c1.y;
        float d2 = sqq + c1.z - 2.0f * dot;
        if (g == q) d2 = 1e30f;

        float thresh = __shfl_sync(0xffffffffu, s_d, 15);
        unsigned ball = __ballot_sync(0xffffffffu, d2 < thresh);
        while (ball) {
            int src = __ffs(ball) - 1;
            ball &= ball - 1;
            float v  = __shfl_sync(0xffffffffu, d2, src);
            int   vi = base + j0 + src;
            float up_d = __shfl_up_sync(0xffffffffu, s_d, 1);
            int   up_i = __shfl_up_sync(0xffffffffu, s_i, 1);
            unsigned lt = __ballot_sync(0xffffffffu, s_d < v);
            int pos = __popc(lt);
            if (pos < 16) {
                if (lane == pos)      { s_d = v;    s_i = vi;   }
                else if (lane > pos)  { s_d = up_d; s_i = up_i; }
            }
        }
    }
    if (lane < 16) nbr[q * KNB + lane] = s_i;
}

// ---------------- layer-1 GEMM (K=6) + direct logits ----------------
__global__ void gemm6_kernel(const float* __restrict__ x, const float* __restrict__ W,
                             const float* __restrict__ a_s, const float* __restrict__ a_d,
                             float* __restrict__ h, float* __restrict__ als,
                             float* __restrict__ ald) {
    __shared__ float sW[6 * 256];
    __shared__ float sAs[256], sAd[256];
    int t = threadIdx.x;
    for (int i = t; i < 6 * 256; i += 256) sW[i] = W[i];
    sAs[t] = a_s[t]; sAd[t] = a_d[t];
    __syncthreads();

    int warp = t >> 5, lane = t & 31;
    int node = blockIdx.x * 8 + warp;
    float xr[6];
#pragma unroll
    for (int d = 0; d < 6; d++) xr[d] = x[node * 6 + d];
    int cbase = lane * 8;
    float out[8];
#pragma unroll
    for (int c = 0; c < 8; c++) {
        float s = 0.f;
#pragma unroll
        for (int d = 0; d < 6; d++) s += xr[d] * sW[d * 256 + cbase + c];
        out[c] = s;
    }
    *(float4*)&h[(size_t)node * 256 + cbase] = make_float4(out[0], out[1], out[2], out[3]);
    *(float4*)&h[(size_t)node * 256 + cbase + 4] = make_float4(out[4], out[5], out[6], out[7]);

    float ps = 0.f, pd = 0.f;
#pragma unroll
    for (int c = 0; c < 8; c++) {
        ps += out[c] * sAs[cbase + c];
        pd += out[c] * sAd[cbase + c];
    }
#pragma unroll
    for (int off = 1; off <= 4; off <<= 1) {
        ps += __shfl_xor_sync(0xffffffffu, ps, off);
        pd += __shfl_xor_sync(0xffffffffu, pd, off);
    }
    if ((lane & 7) == 0) {
        int hh = lane >> 3;
        als[node * 4 + hh] = ps;
        ald[node * 4 + hh] = pd;
    }
}

// ---------------- tf32 tensor-core GEMM: 128x128 tile, 8 warps, fused logits -----
// C[128 rows x 128 cols per block] = A[M,K] @ W[K,N] (+bias)(+gelu)
// K % 32 == 0. If als: logits written directly (H=4: two 64-col heads per block;
// H=1: one head).
__global__ void __launch_bounds__(256) gemm_mma_kernel(
        const float* __restrict__ A, const float* __restrict__ W,
        const float* __restrict__ bias, float* __restrict__ C,
        int K, int N, int actGelu,
        const float* __restrict__ a_s, const float* __restrict__ a_d,
        float* __restrict__ als, float* __restrict__ ald, int H) {
    __shared__ float As[128][36];   // tf32-rounded A tile [m][k]
    __shared__ float Ws[32][136];   // tf32-rounded W tile [k][n]
    __shared__ float s_ls[256], s_ld[256];

    int t = threadIdx.x;
    int warp = t >> 5, lane = t & 31;
    int gid = lane >> 2, tig = lane & 3;
    int wm0 = (warp >> 2) * 64;
    int wn0 = (warp & 3) * 32;
    int row0 = blockIdx.x * 128;
    int c0 = blockIdx.y * 128;

    if (als) { s_ls[t] = 0.f; s_ld[t] = 0.f; }

    float acc[4][4][4];
#pragma unroll
    for (int mt = 0; mt < 4; mt++)
#pragma unroll
        for (int nt = 0; nt < 4; nt++)
#pragma unroll
            for (int r = 0; r < 4; r++) acc[mt][nt][r] = 0.f;

    int aR = t >> 3, aKq = (t & 7) * 4;       // A: rows aR+{0,32,64,96}, k cols aKq..+3
    int wK = t >> 5, wC = (t & 31) * 4;       // W: k rows wK+{0,8,16,24}, n cols wC..+3

    float4 aPf[4], wPf[4];
#pragma unroll
    for (int i = 0; i < 4; i++)
        aPf[i] = *(const float4*)&A[(size_t)(row0 + aR + i * 32) * K + aKq];
#pragma unroll
    for (int i = 0; i < 4; i++)
        wPf[i] = *(const float4*)&W[(size_t)(wK + i * 8) * N + c0 + wC];

    int nch = K >> 5;
    for (int ch = 0; ch < nch; ch++) {
#pragma unroll
        for (int i = 0; i < 4; i++) {
            As[aR + i * 32][aKq + 0] = cvt_tf32(aPf[i].x);
            As[aR + i * 32][aKq + 1] = cvt_tf32(aPf[i].y);
            As[aR + i * 32][aKq + 2] = cvt_tf32(aPf[i].z);
            As[aR + i * 32][aKq + 3] = cvt_tf32(aPf[i].w);
        }
#pragma unroll
        for (int i = 0; i < 4; i++) {
            Ws[wK + i * 8][wC + 0] = cvt_tf32(wPf[i].x);
            Ws[wK + i * 8][wC + 1] = cvt_tf32(wPf[i].y);
            Ws[wK + i * 8][wC + 2] = cvt_tf32(wPf[i].z);
            Ws[wK + i * 8][wC + 3] = cvt_tf32(wPf[i].w);
        }
        __syncthreads();

        if (ch + 1 < nch) {
            int k0 = (ch + 1) << 5;
#pragma unroll
            for (int i = 0; i < 4; i++)
                aPf[i] = *(const float4*)&A[(size_t)(row0 + aR + i * 32) * K + k0 + aKq];
#pragma unroll
            for (int i = 0; i < 4; i++)
                wPf[i] = *(const float4*)&W[(size_t)(k0 + wK + i * 8) * N + c0 + wC];
        }

#pragma unroll
        for (int kk8 = 0; kk8 < 4; kk8++) {
            int kb = kk8 * 8;
            unsigned ua[4][4], ub[4][2];
#pragma unroll
            for (int mt = 0; mt < 4; mt++) {
                int r0 = wm0 + mt * 16 + gid;
                ua[mt][0] = __float_as_uint(As[r0][kb + tig]);
                ua[mt][1] = __float_as_uint(As[r0 + 8][kb + tig]);
                ua[mt][2] = __float_as_uint(As[r0][kb + tig + 4]);
                ua[mt][3] = __float_as_uint(As[r0 + 8][kb + tig + 4]);
            }
#pragma unroll
            for (int nt = 0; nt < 4; nt++) {
                int cn = wn0 + nt * 8 + gid;
                ub[nt][0] = __float_as_uint(Ws[kb + tig][cn]);
                ub[nt][1] = __float_as_uint(Ws[kb + tig + 4][cn]);
            }
#pragma unroll
            for (int mt = 0; mt < 4; mt++)
#pragma unroll
                for (int nt = 0; nt < 4; nt++)
                    mma8(acc[mt][nt], ua[mt], ub[nt]);
        }
        __syncthreads();
    }

    // ---- fused logits ----
    if (als) {
        float asv[4][2], adv[4][2];
#pragma unroll
        for (int nt = 0; nt < 4; nt++) {
            int col = c0 + wn0 + nt * 8 + 2 * tig;
            asv[nt][0] = a_s[col]; asv[nt][1] = a_s[col + 1];
            adv[nt][0] = a_d[col]; adv[nt][1] = a_d[col + 1];
        }
        int lh = (H == 4) ? (wn0 >> 6) : 0;
#pragma unroll
        for (int mt = 0; mt < 4; mt++) {
            float p0s = 0.f, p1s = 0.f, p0d = 0.f, p1d = 0.f;
#pragma unroll
            for (int nt = 0; nt < 4; nt++) {
                p0s += acc[mt][nt][0] * asv[nt][0] + acc[mt][nt][1] * asv[nt][1];
                p1s += acc[mt][nt][2] * asv[nt][0] + acc[mt][nt][3] * asv[nt][1];
                p0d += acc[mt][nt][0] * adv[nt][0] + acc[mt][nt][1] * adv[nt][1];
                p1d += acc[mt][nt][2] * adv[nt][0] + acc[mt][nt][3] * adv[nt][1];
            }
#pragma unroll
            for (int off = 1; off <= 2; off <<= 1) {
                p0s += __shfl_xor_sync(0xffffffffu, p0s, off);
                p1s += __shfl_xor_sync(0xffffffffu, p1s, off);
                p0d += __shfl_xor_sync(0xffffffffu, p0d, off);
                p1d += __shfl_xor_sync(0xffffffffu, p1d, off);
            }
            if (tig == 0) {
                int rl = wm0 + mt * 16 + gid;
                atomicAdd(&s_ls[lh * 128 + rl], p0s);
                atomicAdd(&s_ls[lh * 128 + rl + 8], p1s);
                atomicAdd(&s_ld[lh * 128 + rl], p0d);
                atomicAdd(&s_ld[lh * 128 + rl + 8], p1d);
            }
        }
        __syncthreads();
        if (H == 4) {
            int row = t & 127, hh = (c0 >> 6) + (t >> 7);
            als[(size_t)(row0 + row) * 4 + hh] = s_ls[(t >> 7) * 128 + row];
            ald[(size_t)(row0 + row) * 4 + hh] = s_ld[(t >> 7) * 128 + row];
        } else if (t < 128) {
            als[row0 + t] = s_ls[t];
            ald[row0 + t] = s_ld[t];
        }
    }

    // ---- bias + gelu + store ----
    float bb[4][2];
#pragma unroll
    for (int nt = 0; nt < 4; nt++) {
        if (bias) {
            int col = c0 + wn0 + nt * 8 + 2 * tig;
            bb[nt][0] = bias[col]; bb[nt][1] = bias[col + 1];
        } else { bb[nt][0] = 0.f; bb[nt][1] = 0.f; }
    }
#pragma unroll
    for (int mt = 0; mt < 4; mt++) {
#pragma unroll
        for (int rs = 0; rs < 2; rs++) {
            int row = row0 + wm0 + mt * 16 + gid + rs * 8;
            float* dst = &C[(size_t)row * N + c0 + wn0];
#pragma unroll
            for (int nt = 0; nt < 4; nt++) {
                float v0 = acc[mt][nt][2 * rs] + bb[nt][0];
                float v1 = acc[mt][nt][2 * rs + 1] + bb[nt][1];
                if (actGelu) { v0 = geluf(v0); v1 = geluf(v1); }
                *(float2*)&dst[nt * 8 + 2 * tig] = make_float2(v0, v1);
            }
        }
    }
}

// ---------------- 128x64 FFMA GEMM (MLP layer 2, N=64) ----------------
__global__ void gemm_tile_kernel(const float* __restrict__ A, const float* __restrict__ W,
                                 const float* __restrict__ bias, float* __restrict__ C,
                                 int K, int N, int actGelu) {
    __shared__ float As[16][136];
    __shared__ float Ws[16][64];

    int t = threadIdx.x;
    int tx = t & 15;
    int ty = t >> 4;
    int row0 = blockIdx.x * 128;
    int c0 = blockIdx.y * 64;

    float acc[8][4];
#pragma unroll
    for (int r = 0; r < 8; r++)
#pragma unroll
        for (int c = 0; c < 4; c++) acc[r][c] = 0.f;

    float4 aReg[2], wReg;
    int aR[2], aKq[2];
#pragma unroll
    for (int i = 0; i < 2; i++) {
        int lin = t + i * 256;
        aR[i] = lin >> 2;
        aKq[i] = lin & 3;
    }
    int wK = t >> 4, wC = (t & 15) * 4;

#pragma unroll
    for (int i = 0; i < 2; i++)
        aReg[i] = *(const float4*)&A[(size_t)(row0 + aR[i]) * K + aKq[i] * 4];
    wReg = *(const float4*)&W[(size_t)wK * N + c0 + wC];

    int nchunks = K >> 4;
    for (int ch = 0; ch < nchunks; ch++) {
#pragma unroll
        for (int i = 0; i < 2; i++) {
            As[aKq[i] * 4 + 0][aR[i]] = aReg[i].x;
            As[aKq[i] * 4 + 1][aR[i]] = aReg[i].y;
            As[aKq[i] * 4 + 2][aR[i]] = aReg[i].z;
            As[aKq[i] * 4 + 3][aR[i]] = aReg[i].w;
        }
        *(float4*)&Ws[wK][wC] = wReg;
        __syncthreads();

        if (ch + 1 < nchunks) {
            int k0 = (ch + 1) << 4;
#pragma unroll
            for (int i = 0; i < 2; i++)
                aReg[i] = *(const float4*)&A[(size_t)(row0 + aR[i]) * K + k0 + aKq[i] * 4];
            wReg = *(const float4*)&W[(size_t)(k0 + wK) * N + c0 + wC];
        }

#pragma unroll
        for (int k = 0; k < 16; k++) {
            float4 a0 = *(const float4*)&As[k][ty * 8];
            float4 a1 = *(const float4*)&As[k][ty * 8 + 4];
            float4 wv = *(const float4*)&Ws[k][tx * 4];
            acc[0][0] += a0.x * wv.x; acc[0][1] += a0.x * wv.y; acc[0][2] += a0.x * wv.z; acc[0][3] += a0.x * wv.w;
            acc[1][0] += a0.y * wv.x; acc[1][1] += a0.y * wv.y; acc[1][2] += a0.y * wv.z; acc[1][3] += a0.y * wv.w;
            acc[2][0] += a0.z * wv.x; acc[2][1] += a0.z * wv.y; acc[2][2] += a0.z * wv.z; acc[2][3] += a0.z * wv.w;
            acc[3][0] += a0.w * wv.x; acc[3][1] += a0.w * wv.y; acc[3][2] += a0.w * wv.z; acc[3][3] += a0.w * wv.w;
            acc[4][0] += a1.x * wv.x; acc[4][1] += a1.x * wv.y; acc[4][2] += a1.x * wv.z; acc[4][3] += a1.x * wv.w;
            acc[5][0] += a1.y * wv.x; acc[5][1] += a1.y * wv.y; acc[5][2] += a1.y * wv.z; acc[5][3] += a1.y * wv.w;
            acc[6][0] += a1.z * wv.x; acc[6][1] += a1.z * wv.y; acc[6][2] += a1.z * wv.z; acc[6][3] += a1.z * wv.w;
            acc[7][0] += a1.w * wv.x; acc[7][1] += a1.w * wv.y; acc[7][2] += a1.w * wv.z; acc[7][3] += a1.w * wv.w;
        }
        __syncthreads();
    }

    float4 bb = make_float4(0.f, 0.f, 0.f, 0.f);
    if (bias) bb = *(const float4*)&bias[c0 + tx * 4];
#pragma unroll
    for (int r = 0; r < 8; r++) {
        float v0 = acc[r][0] + bb.x, v1 = acc[r][1] + bb.y,
              v2 = acc[r][2] + bb.z, v3 = acc[r][3] + bb.w;
        if (actGelu) { v0 = geluf(v0); v1 = geluf(v1); v2 = geluf(v2); v3 = geluf(v3); }
        *(float4*)&C[(size_t)(row0 + ty * 8 + r) * N + c0 + tx * 4] =
            make_float4(v0, v1, v2, v3);
    }
}

// ---------------- warp-per-node GAT aggregate (H=4, F=256) ----------------
__global__ void warp_agg4_kernel(const float* __restrict__ h, const int* __restrict__ nbr,
                                 const float* __restrict__ als, const float* __restrict__ ald,
                                 const float* __restrict__ bias, float* __restrict__ out) {
    __shared__ float s_alpha[8][68];
    int warp = threadIdx.x >> 5, lane = threadIdx.x & 31;
    int i = blockIdx.x * 8 + warp;

    int nbr_j = i;
    if (lane < 16) nbr_j = nbr[i * KNB + lane];

    float4 sv = *(const float4*)&als[nbr_j * 4];
    float4 dv = *(const float4*)&ald[i * 4];
    float e0 = sv.x + dv.x, e1 = sv.y + dv.y, e2 = sv.z + dv.z, e3 = sv.w + dv.w;
    e0 = e0 > 0.f ? e0 : 0.2f * e0;
    e1 = e1 > 0.f ? e1 : 0.2f * e1;
    e2 = e2 > 0.f ? e2 : 0.2f * e2;
    e3 = e3 > 0.f ? e3 : 0.2f * e3;
    float m0 = lane < 17 ? e0 : -1e30f, m1 = lane < 17 ? e1 : -1e30f;
    float m2 = lane < 17 ? e2 : -1e30f, m3 = lane < 17 ? e3 : -1e30f;
#pragma unroll
    for (int off = 16; off > 0; off >>= 1) {
        m0 = fmaxf(m0, __shfl_xor_sync(0xffffffffu, m0, off));
        m1 = fmaxf(m1, __shfl_xor_sync(0xffffffffu, m1, off));
        m2 = fmaxf(m2, __shfl_xor_sync(0xffffffffu, m2, off));
        m3 = fmaxf(m3, __shfl_xor_sync(0xffffffffu, m3, off));
    }
    float x0 = lane < 17 ? __expf(e0 - m0) : 0.f;
    float x1 = lane < 17 ? __expf(e1 - m1) : 0.f;
    float x2 = lane < 17 ? __expf(e2 - m2) : 0.f;
    float x3 = lane < 17 ? __expf(e3 - m3) : 0.f;
    float d0 = x0, d1 = x1, d2 = x2, d3 = x3;
#pragma unroll
    for (int off = 16; off > 0; off >>= 1) {
        d0 += __shfl_xor_sync(0xffffffffu, d0, off);
        d1 += __shfl_xor_sync(0xffffffffu, d1, off);
        d2 += __shfl_xor_sync(0xffffffffu, d2, off);
        d3 += __shfl_xor_sync(0xffffffffu, d3, off);
    }
    if (lane < 17) {
        s_alpha[warp][0 * 17 + lane] = x0 / d0;
        s_alpha[warp][1 * 17 + lane] = x1 / d1;
        s_alpha[warp][2 * 17 + lane] = x2 / d2;
        s_alpha[warp][3 * 17 + lane] = x3 / d3;
    }
    __syncwarp();

    int fbase = lane * 8;
    int hh = lane >> 3;
    float4 acc0 = make_float4(0.f, 0.f, 0.f, 0.f);
    float4 acc1 = make_float4(0.f, 0.f, 0.f, 0.f);
#pragma unroll
    for (int j = 0; j < 17; j++) {
        int g = __shfl_sync(0xffffffffu, nbr_j, j);
        float a = s_alpha[warp][hh * 17 + j];
        const float4* p = (const float4*)(h + g * 256 + fbase);
        float4 v0 = p[0], v1 = p[1];
        acc0.x += a * v0.x; acc0.y += a * v0.y; acc0.z += a * v0.z; acc0.w += a * v0.w;
        acc1.x += a * v1.x; acc1.y += a * v1.y; acc1.z += a * v1.z; acc1.w += a * v1.w;
    }
    float4 b0 = *(const float4*)&bias[fbase];
    float4 b1 = *(const float4*)&bias[fbase + 4];
    float4 o0 = make_float4(geluf(acc0.x + b0.x), geluf(acc0.y + b0.y),
                            geluf(acc0.z + b0.z), geluf(acc0.w + b0.w));
    float4 o1 = make_float4(geluf(acc1.x + b1.x), geluf(acc1.y + b1.y),
                            geluf(acc1.z + b1.z), geluf(acc1.w + b1.w));
    *(float4*)&out[i * 256 + fbase] = o0;
    *(float4*)&out[i * 256 + fbase + 4] = o1;
}

// ---------------- warp-per-node GAT aggregate (H=1, F=128) + residual -------------
__global__ void warp_agg1_kernel(const float* __restrict__ h, const int* __restrict__ nbr,
                                 const float* __restrict__ als, const float* __restrict__ ald,
                                 const float* __restrict__ bias, float* __restrict__ out,
                                 const float* __restrict__ x6, const float* __restrict__ resW,
                                 const float* __restrict__ resb) {
    int warp = threadIdx.x >> 5, lane = threadIdx.x & 31;
    int i = blockIdx.x * 8 + warp;

    int nbr_j = i;
    if (lane < 16) nbr_j = nbr[i * KNB + lane];

    float e = als[nbr_j] + ald[i];
    e = e > 0.f ? e : 0.2f * e;
    float m = lane < 17 ? e : -1e30f;
#pragma unroll
    for (int off = 16; off > 0; off >>= 1)
        m = fmaxf(m, __shfl_xor_sync(0xffffffffu, m, off));
    float xe = lane < 17 ? __expf(e - m) : 0.f;
    float den = xe;
#pragma unroll
    for (int off = 16; off > 0; off >>= 1)
        den += __shfl_xor_sync(0xffffffffu, den, off);
    float alpha = xe / den;

    int fbase = lane * 4;
    float4 acc = make_float4(0.f, 0.f, 0.f, 0.f);
#pragma unroll
    for (int j = 0; j < 17; j++) {
        int g = __shfl_sync(0xffffffffu, nbr_j, j);
        float a = __shfl_sync(0xffffffffu, alpha, j);
        float4 v = *(const float4*)(h + g * 128 + fbase);
        acc.x += a * v.x; acc.y += a * v.y; acc.z += a * v.z; acc.w += a * v.w;
    }
    float4 bb = *(const float4*)&bias[fbase];
    float4 o = make_float4(geluf(acc.x + bb.x), geluf(acc.y + bb.y),
                           geluf(acc.z + bb.z), geluf(acc.w + bb.w));
    float4 r = *(const float4*)&resb[fbase];
#pragma unroll
    for (int d = 0; d < 6; d++) {
        float xv = x6[i * 6 + d];
        float4 w = *(const float4*)&resW[d * 128 + fbase];
        r.x += xv * w.x; r.y += xv * w.y; r.z += xv * w.z; r.w += xv * w.w;
    }
    o.x += r.x; o.y += r.y; o.z += r.z; o.w += r.w;
    *(float4*)&out[i * 128 + fbase] = o;
}

// ---------------- final ----------------
__global__ void final_kernel(const float* __restrict__ A, const float* __restrict__ W,
                             const float* __restrict__ b, float* __restrict__ out) {
    __shared__ float Ws[64 * 6];
    __shared__ float sb[6];
    int t = threadIdx.x;
    for (int k = t; k < 64 * 6; k += blockDim.x) Ws[k] = W[k];
    if (t < 6) sb[t] = b[t];
    __syncthreads();

    int i = blockIdx.x * blockDim.x + t;
    if (i >= NN) return;
    float acc[6];
#pragma unroll
    for (int o = 0; o < 6; o++) acc[o] = sb[o];
    const float4* Ar = (const float4*)(A + (size_t)i * 64);
#pragma unroll
    for (int k4 = 0; k4 < 16; k4++) {
        float4 v = Ar[k4];
        int k = k4 * 4;
#pragma unroll
        for (int o = 0; o < 6; o++) {
            acc[o] += v.x * Ws[(k + 0) * 6 + o];
            acc[o] += v.y * Ws[(k + 1) * 6 + o];
            acc[o] += v.z * Ws[(k + 2) * 6 + o];
            acc[o] += v.w * Ws[(k + 3) * 6 + o];
        }
    }
#pragma unroll
    for (int o = 0; o < 6; o++) out[(size_t)i * 6 + o] = acc[o];
}

// ---------------- launch ----------------
extern "C" void kernel_launch(void* const* d_in, const int* in_sizes, int n_in,
                              void* d_out, int out_size) {
    const float* x    = (const float*)d_in[0];
    const float* W1   = (const float*)d_in[1];
    const float* as1  = (const float*)d_in[2];
    const float* ad1  = (const float*)d_in[3];
    const float* b1   = (const float*)d_in[4];
    const float* W2   = (const float*)d_in[5];
    const float* as2  = (const float*)d_in[6];
    const float* ad2  = (const float*)d_in[7];
    const float* b2   = (const float*)d_in[8];
    const float* W3   = (const float*)d_in[9];
    const float* as3  = (const float*)d_in[10];
    const float* ad3  = (const float*)d_in[11];
    const float* b3   = (const float*)d_in[12];
    const float* resW = (const float*)d_in[13];
    const float* resb = (const float*)d_in[14];
    const float* m1W  = (const float*)d_in[15];
    const float* m1b  = (const float*)d_in[16];
    const float* m2W  = (const float*)d_in[17];
    const float* m2b  = (const float*)d_in[18];
    const float* m3W  = (const float*)d_in[19];
    const float* m3b  = (const float*)d_in[20];

    float *xp, *h, *a0, *a1, *als, *ald;
    int* nbr;
    cudaGetSymbolAddress((void**)&xp,  g_xp);
    cudaGetSymbolAddress((void**)&nbr, g_nbr);
    cudaGetSymbolAddress((void**)&h,   g_h);
    cudaGetSymbolAddress((void**)&a0,  g_act0);
    cudaGetSymbolAddress((void**)&a1,  g_act1);
    cudaGetSymbolAddress((void**)&als, g_als);
    cudaGetSymbolAddress((void**)&ald, g_ald);

    prep_kernel<<<NN / 256, 256>>>(x, xp);
    knn_kernel<<<NN / 8, 256>>>(xp, nbr);

    // GAT layer 1 (6 -> 256, H=4)
    gemm6_kernel<<<NN / 8, 256>>>(x, W1, as1, ad1, h, als, ald);
    warp_agg4_kernel<<<NN / 8, 256>>>(h, nbr, als, ald, b1, a0);

    // GAT layer 2 (256 -> 256, H=4): tf32 MMA + fused logits
    gemm_mma_kernel<<<dim3(NN / 128, 2), 256>>>(a0, W2, nullptr, h, 256, 256, 0,
                                                as2, ad2, als, ald, 4);
    warp_agg4_kernel<<<NN / 8, 256>>>(h, nbr, als, ald, b2, a1);

    // GAT layer 3 (256 -> 128, H=1) + fused residual
    gemm_mma_kernel<<<dim3(NN / 128, 1), 256>>>(a1, W3, nullptr, h, 256, 128, 0,
                                                as3, ad3, als, ald, 1);
    warp_agg1_kernel<<<NN / 8, 256>>>(h, nbr, als, ald, b3, a0, x, resW, resb);

    // MLP
    gemm_mma_kernel<<<dim3(NN / 128, 1), 256>>>(a0, m1W, m1b, a1, 128, 128, 1,
                                                nullptr, nullptr, nullptr, nullptr, 0);
    gemm_tile_kernel<<<dim3(NN / 128, 1), 256>>>(a1, m2W, m2b, h, 128, 64, 1);
    final_kernel<<<NN / 128, 128>>>(h, m3W, m3b, (float*)d_out);
}

// round 9
// speedup vs baseline: 1.5086x; 1.0112x over previous
#include <cuda_runtime.h>
#include <math.h>

#define NN 16384      // total nodes (B*N)
#define NB 4096       // nodes per batch
#define KNB 16        // kNN K

// ---------------- scratch ----------------
__device__ float g_xp[NN * 8];
__device__ int   g_nbr[NN * KNB];
__device__ float g_h[NN * 256];
__device__ float g_act0[NN * 256];
__device__ float g_act1[NN * 256];
__device__ float g_als[NN * 4];
__device__ float g_ald[NN * 4];

__device__ __forceinline__ float geluf(float v) {
    return 0.5f * v * (1.0f + erff(v * 0.7071067811865476f));
}

// fp32 -> tf32 (RNA rounding), bit pattern returned as float
__device__ __forceinline__ float cvt_tf32(float x) {
    unsigned r;
    asm("cvt.rna.tf32.f32 %0, %1;" : "=r"(r) : "f"(x));
    return __uint_as_float(r);
}

// one m16n8k8 tf32 MMA, D += A*B
__device__ __forceinline__ void mma8(float* d, const unsigned* a, const unsigned* b) {
    asm volatile(
        "mma.sync.aligned.m16n8k8.row.col.f32.tf32.tf32.f32 "
        "{%0,%1,%2,%3}, {%4,%5,%6,%7}, {%8,%9}, {%0,%1,%2,%3};"
        : "+f"(d[0]), "+f"(d[1]), "+f"(d[2]), "+f"(d[3])
        : "r"(a[0]), "r"(a[1]), "r"(a[2]), "r"(a[3]), "r"(b[0]), "r"(b[1]));
}

// ---------------- prep ----------------
__global__ void prep_kernel(const float* __restrict__ x, float* __restrict__ xp) {
    int i = blockIdx.x * blockDim.x + threadIdx.x;
    if (i >= NN) return;
    float s = 0.f;
    float v[6];
#pragma unroll
    for (int d = 0; d < 6; d++) { v[d] = x[i * 6 + d]; s += v[d] * v[d]; }
#pragma unroll
    for (int d = 0; d < 6; d++) xp[i * 8 + d] = v[d];
    xp[i * 8 + 6] = s;
    xp[i * 8 + 7] = 0.f;
}

// ---------------- kNN: warp handles TWO queries; shared candidate loads ---------
// Distributed sorted top-16 lists: lanes 0..15 hold q0's list, lanes 16..31 q1's.
__global__ void knn_kernel(const float* __restrict__ xp, int* __restrict__ nbr) {
    int gwarp = (blockIdx.x * blockDim.x + threadIdx.x) >> 5;
    int lane = threadIdx.x & 31;
    int q0 = gwarp * 2, q1 = q0 + 1;
    int base = q0 & ~(NB - 1);

    const float4* xp4 = (const float4*)xp;
    float4 qa0 = xp4[(size_t)q0 * 2], qa1 = xp4[(size_t)q0 * 2 + 1];
    float4 qb0 = xp4[(size_t)q1 * 2], qb1 = xp4[(size_t)q1 * 2 + 1];
    float sqa = qa1.z, sqb = qb1.z;

    float s_d = 1e30f;
    int   s_i = -1;
    int ll = lane & 15;

    for (int j0 = 0; j0 < NB; j0 += 32) {
        int g = base + j0 + lane;
        float4 c0 = xp4[(size_t)g * 2];
        float4 c1 = xp4[(size_t)g * 2 + 1];
        float dota = qa0.x * c0.x + qa0.y * c0.y + qa0.z * c0.z + qa0.w * c0.w
                   + qa1.x * c1.x + qa1.y * c1.y;
        float dotb = qb0.x * c0.x + qb0.y * c0.y + qb0.z * c0.z + qb0.w * c0.w
                   + qb1.x * c1.x + qb1.y * c1.y;
        float da = sqa + c1.z - 2.0f * dota;
        float db = sqb + c1.z - 2.0f * dotb;
        if (g == q0) da = 1e30f;
        if (g == q1) db = 1e30f;

        float ta = __shfl_sync(0xffffffffu, s_d, 15);
        float tb = __shfl_sync(0xffffffffu, s_d, 31);
        unsigned ba = __ballot_sync(0xffffffffu, da < ta);
        unsigned bb = __ballot_sync(0xffffffffu, db < tb);
        unsigned ball = ba | bb;
        while (ball) {
            int src = __ffs(ball) - 1;
            ball &= ball - 1;
            float va = __shfl_sync(0xffffffffu, da, src);
            float vb = __shfl_sync(0xffffffffu, db, src);
            float v = (lane < 16) ? va : vb;
            bool act = (lane < 16) ? ((ba >> src) & 1u) : ((bb >> src) & 1u);
            float up_d = __shfl_up_sync(0xffffffffu, s_d, 1, 16);
            int   up_i = __shfl_up_sync(0xffffffffu, s_i, 1, 16);
            unsigned lt = __ballot_sync(0xffffffffu, s_d < v);
            int pos = (lane < 16) ? __popc(lt & 0xFFFFu) : __popc(lt >> 16);
            if (act && pos < 16) {
                if (ll == pos)      { s_d = v;    s_i = base + j0 + src; }
                else if (ll > pos)  { s_d = up_d; s_i = up_i; }
            }
        }
    }
    if (lane < 16) nbr[q0 * KNB + ll] = s_i;
    else           nbr[q1 * KNB + ll] = s_i;
}

// ---------------- layer-1 GEMM (K=6) + direct logits ----------------
__global__ void gemm6_kernel(const float* __restrict__ x, const float* __restrict__ W,
                             const float* __restrict__ a_s, const float* __restrict__ a_d,
                             float* __restrict__ h, float* __restrict__ als,
                             float* __restrict__ ald) {
    __shared__ float sW[6 * 256];
    __shared__ float sAs[256], sAd[256];
    int t = threadIdx.x;
    for (int i = t; i < 6 * 256; i += 256) sW[i] = W[i];
    sAs[t] = a_s[t]; sAd[t] = a_d[t];
    __syncthreads();

    int warp = t >> 5, lane = t & 31;
    int node = blockIdx.x * 8 + warp;
    float xr[6];
#pragma unroll
    for (int d = 0; d < 6; d++) xr[d] = x[node * 6 + d];
    int cbase = lane * 8;
    float out[8];
#pragma unroll
    for (int c = 0; c < 8; c++) {
        float s = 0.f;
#pragma unroll
        for (int d = 0; d < 6; d++) s += xr[d] * sW[d * 256 + cbase + c];
        out[c] = s;
    }
    *(float4*)&h[(size_t)node * 256 + cbase] = make_float4(out[0], out[1], out[2], out[3]);
    *(float4*)&h[(size_t)node * 256 + cbase + 4] = make_float4(out[4], out[5], out[6], out[7]);

    float ps = 0.f, pd = 0.f;
#pragma unroll
    for (int c = 0; c < 8; c++) {
        ps += out[c] * sAs[cbase + c];
        pd += out[c] * sAd[cbase + c];
    }
#pragma unroll
    for (int off = 1; off <= 4; off <<= 1) {
        ps += __shfl_xor_sync(0xffffffffu, ps, off);
        pd += __shfl_xor_sync(0xffffffffu, pd, off);
    }
    if ((lane & 7) == 0) {
        int hh = lane >> 3;
        als[node * 4 + hh] = ps;
        ald[node * 4 + hh] = pd;
    }
}

// ---------------- tf32 tensor-core GEMM: 128x128 tile, 8 warps, fused logits -----
__global__ void __launch_bounds__(256) gemm_mma_kernel(
        const float* __restrict__ A, const float* __restrict__ W,
        const float* __restrict__ bias, float* __restrict__ C,
        int K, int N, int actGelu,
        const float* __restrict__ a_s, const float* __restrict__ a_d,
        float* __restrict__ als, float* __restrict__ ald, int H) {
    __shared__ float As[128][36];   // tf32-rounded A tile [m][k]
    __shared__ float Ws[32][136];   // tf32-rounded W tile [k][n]
    __shared__ float s_ls[256], s_ld[256];

    int t = threadIdx.x;
    int warp = t >> 5, lane = t & 31;
    int gid = lane >> 2, tig = lane & 3;
    int wm0 = (warp >> 2) * 64;
    int wn0 = (warp & 3) * 32;
    int row0 = blockIdx.x * 128;
    int c0 = blockIdx.y * 128;

    if (als) { s_ls[t] = 0.f; s_ld[t] = 0.f; }

    float acc[4][4][4];
#pragma unroll
    for (int mt = 0; mt < 4; mt++)
#pragma unroll
        for (int nt = 0; nt < 4; nt++)
#pragma unroll
            for (int r = 0; r < 4; r++) acc[mt][nt][r] = 0.f;

    int aR = t >> 3, aKq = (t & 7) * 4;
    int wK = t >> 5, wC = (t & 31) * 4;

    float4 aPf[4], wPf[4];
#pragma unroll
    for (int i = 0; i < 4; i++)
        aPf[i] = *(const float4*)&A[(size_t)(row0 + aR + i * 32) * K + aKq];
#pragma unroll
    for (int i = 0; i < 4; i++)
        wPf[i] = *(const float4*)&W[(size_t)(wK + i * 8) * N + c0 + wC];

    int nch = K >> 5;
    for (int ch = 0; ch < nch; ch++) {
#pragma unroll
        for (int i = 0; i < 4; i++) {
            As[aR + i * 32][aKq + 0] = cvt_tf32(aPf[i].x);
            As[aR + i * 32][aKq + 1] = cvt_tf32(aPf[i].y);
            As[aR + i * 32][aKq + 2] = cvt_tf32(aPf[i].z);
            As[aR + i * 32][aKq + 3] = cvt_tf32(aPf[i].w);
        }
#pragma unroll
        for (int i = 0; i < 4; i++) {
            Ws[wK + i * 8][wC + 0] = cvt_tf32(wPf[i].x);
            Ws[wK + i * 8][wC + 1] = cvt_tf32(wPf[i].y);
            Ws[wK + i * 8][wC + 2] = cvt_tf32(wPf[i].z);
            Ws[wK + i * 8][wC + 3] = cvt_tf32(wPf[i].w);
        }
        __syncthreads();

        if (ch + 1 < nch) {
            int k0 = (ch + 1) << 5;
#pragma unroll
            for (int i = 0; i < 4; i++)
                aPf[i] = *(const float4*)&A[(size_t)(row0 + aR + i * 32) * K + k0 + aKq];
#pragma unroll
            for (int i = 0; i < 4; i++)
                wPf[i] = *(const float4*)&W[(size_t)(k0 + wK + i * 8) * N + c0 + wC];
        }

#pragma unroll
        for (int kk8 = 0; kk8 < 4; kk8++) {
            int kb = kk8 * 8;
            unsigned ua[4][4], ub[4][2];
#pragma unroll
            for (int mt = 0; mt < 4; mt++) {
                int r0 = wm0 + mt * 16 + gid;
                ua[mt][0] = __float_as_uint(As[r0][kb + tig]);
                ua[mt][1] = __float_as_uint(As[r0 + 8][kb + tig]);
                ua[mt][2] = __float_as_uint(As[r0][kb + tig + 4]);
                ua[mt][3] = __float_as_uint(As[r0 + 8][kb + tig + 4]);
            }
#pragma unroll
            for (int nt = 0; nt < 4; nt++) {
                int cn = wn0 + nt * 8 + gid;
                ub[nt][0] = __float_as_uint(Ws[kb + tig][cn]);
                ub[nt][1] = __float_as_uint(Ws[kb + tig + 4][cn]);
            }
#pragma unroll
            for (int mt = 0; mt < 4; mt++)
#pragma unroll
                for (int nt = 0; nt < 4; nt++)
                    mma8(acc[mt][nt], ua[mt], ub[nt]);
        }
        __syncthreads();
    }

    // ---- fused logits ----
    if (als) {
        float asv[4][2], adv[4][2];
#pragma unroll
        for (int nt = 0; nt < 4; nt++) {
            int col = c0 + wn0 + nt * 8 + 2 * tig;
            asv[nt][0] = a_s[col]; asv[nt][1] = a_s[col + 1];
            adv[nt][0] = a_d[col]; adv[nt][1] = a_d[col + 1];
        }
        int lh = (H == 4) ? (wn0 >> 6) : 0;
#pragma unroll
        for (int mt = 0; mt < 4; mt++) {
            float p0s = 0.f, p1s = 0.f, p0d = 0.f, p1d = 0.f;
#pragma unroll
            for (int nt = 0; nt < 4; nt++) {
                p0s += acc[mt][nt][0] * asv[nt][0] + acc[mt][nt][1] * asv[nt][1];
                p1s += acc[mt][nt][2] * asv[nt][0] + acc[mt][nt][3] * asv[nt][1];
                p0d += acc[mt][nt][0] * adv[nt][0] + acc[mt][nt][1] * adv[nt][1];
                p1d += acc[mt][nt][2] * adv[nt][0] + acc[mt][nt][3] * adv[nt][1];
            }
#pragma unroll
            for (int off = 1; off <= 2; off <<= 1) {
                p0s += __shfl_xor_sync(0xffffffffu, p0s, off);
                p1s += __shfl_xor_sync(0xffffffffu, p1s, off);
                p0d += __shfl_xor_sync(0xffffffffu, p0d, off);
                p1d += __shfl_xor_sync(0xffffffffu, p1d, off);
            }
            if (tig == 0) {
                int rl = wm0 + mt * 16 + gid;
                atomicAdd(&s_ls[lh * 128 + rl], p0s);
                atomicAdd(&s_ls[lh * 128 + rl + 8], p1s);
                atomicAdd(&s_ld[lh * 128 + rl], p0d);
                atomicAdd(&s_ld[lh * 128 + rl + 8], p1d);
            }
        }
        __syncthreads();
        if (H == 4) {
            int row = t & 127, hh = (c0 >> 6) + (t >> 7);
            als[(size_t)(row0 + row) * 4 + hh] = s_ls[(t >> 7) * 128 + row];
            ald[(size_t)(row0 + row) * 4 + hh] = s_ld[(t >> 7) * 128 + row];
        } else if (t < 128) {
            als[row0 + t] = s_ls[t];
            ald[row0 + t] = s_ld[t];
        }
    }

    // ---- bias + gelu + store ----
    float bb[4][2];
#pragma unroll
    for (int nt = 0; nt < 4; nt++) {
        if (bias) {
            int col = c0 + wn0 + nt * 8 + 2 * tig;
            bb[nt][0] = bias[col]; bb[nt][1] = bias[col + 1];
        } else { bb[nt][0] = 0.f; bb[nt][1] = 0.f; }
    }
#pragma unroll
    for (int mt = 0; mt < 4; mt++) {
#pragma unroll
        for (int rs = 0; rs < 2; rs++) {
            int row = row0 + wm0 + mt * 16 + gid + rs * 8;
            float* dst = &C[(size_t)row * N + c0 + wn0];
#pragma unroll
            for (int nt = 0; nt < 4; nt++) {
                float v0 = acc[mt][nt][2 * rs] + bb[nt][0];
                float v1 = acc[mt][nt][2 * rs + 1] + bb[nt][1];
                if (actGelu) { v0 = geluf(v0); v1 = geluf(v1); }
                *(float2*)&dst[nt * 8 + 2 * tig] = make_float2(v0, v1);
            }
        }
    }
}

// ---------------- 128x64 FFMA GEMM (MLP layer 2, N=64) ----------------
__global__ void gemm_tile_kernel(const float* __restrict__ A, const float* __restrict__ W,
                                 const float* __restrict__ bias, float* __restrict__ C,
                                 int K, int N, int actGelu) {
    __shared__ float As[16][136];
    __shared__ float Ws[16][64];

    int t = threadIdx.x;
    int tx = t & 15;
    int ty = t >> 4;
    int row0 = blockIdx.x * 128;
    int c0 = blockIdx.y * 64;

    float acc[8][4];
#pragma unroll
    for (int r = 0; r < 8; r++)
#pragma unroll
        for (int c = 0; c < 4; c++) acc[r][c] = 0.f;

    float4 aReg[2], wReg;
    int aR[2], aKq[2];
#pragma unroll
    for (int i = 0; i < 2; i++) {
        int lin = t + i * 256;
        aR[i] = lin >> 2;
        aKq[i] = lin & 3;
    }
    int wK = t >> 4, wC = (t & 15) * 4;

#pragma unroll
    for (int i = 0; i < 2; i++)
        aReg[i] = *(const float4*)&A[(size_t)(row0 + aR[i]) * K + aKq[i] * 4];
    wReg = *(const float4*)&W[(size_t)wK * N + c0 + wC];

    int nchunks = K >> 4;
    for (int ch = 0; ch < nchunks; ch++) {
#pragma unroll
        for (int i = 0; i < 2; i++) {
            As[aKq[i] * 4 + 0][aR[i]] = aReg[i].x;
            As[aKq[i] * 4 + 1][aR[i]] = aReg[i].y;
            As[aKq[i] * 4 + 2][aR[i]] = aReg[i].z;
            As[aKq[i] * 4 + 3][aR[i]] = aReg[i].w;
        }
        *(float4*)&Ws[wK][wC] = wReg;
        __syncthreads();

        if (ch + 1 < nchunks) {
            int k0 = (ch + 1) << 4;
#pragma unroll
            for (int i = 0; i < 2; i++)
                aReg[i] = *(const float4*)&A[(size_t)(row0 + aR[i]) * K + k0 + aKq[i] * 4];
            wReg = *(const float4*)&W[(size_t)(k0 + wK) * N + c0 + wC];
        }

#pragma unroll
        for (int k = 0; k < 16; k++) {
            float4 a0 = *(const float4*)&As[k][ty * 8];
            float4 a1 = *(const float4*)&As[k][ty * 8 + 4];
            float4 wv = *(const float4*)&Ws[k][tx * 4];
            acc[0][0] += a0.x * wv.x; acc[0][1] += a0.x * wv.y; acc[0][2] += a0.x * wv.z; acc[0][3] += a0.x * wv.w;
            acc[1][0] += a0.y * wv.x; acc[1][1] += a0.y * wv.y; acc[1][2] += a0.y * wv.z; acc[1][3] += a0.y * wv.w;
            acc[2][0] += a0.z * wv.x; acc[2][1] += a0.z * wv.y; acc[2][2] += a0.z * wv.z; acc[2][3] += a0.z * wv.w;
            acc[3][0] += a0.w * wv.x; acc[3][1] += a0.w * wv.y; acc[3][2] += a0.w * wv.z; acc[3][3] += a0.w * wv.w;
            acc[4][0] += a1.x * wv.x; acc[4][1] += a1.x * wv.y; acc[4][2] += a1.x * wv.z; acc[4][3] += a1.x * wv.w;
            acc[5][0] += a1.y * wv.x; acc[5][1] += a1.y * wv.y; acc[5][2] += a1.y * wv.z; acc[5][3] += a1.y * wv.w;
            acc[6][0] += a1.z * wv.x; acc[6][1] += a1.z * wv.y; acc[6][2] += a1.z * wv.z; acc[6][3] += a1.z * wv.w;
            acc[7][0] += a1.w * wv.x; acc[7][1] += a1.w * wv.y; acc[7][2] += a1.w * wv.z; acc[7][3] += a1.w * wv.w;
        }
        __syncthreads();
    }

    float4 bb = make_float4(0.f, 0.f, 0.f, 0.f);
    if (bias) bb = *(const float4*)&bias[c0 + tx * 4];
#pragma unroll
    for (int r = 0; r < 8; r++) {
        float v0 = acc[r][0] + bb.x, v1 = acc[r][1] + bb.y,
              v2 = acc[r][2] + bb.z, v3 = acc[r][3] + bb.w;
        if (actGelu) { v0 = geluf(v0); v1 = geluf(v1); v2 = geluf(v2); v3 = geluf(v3); }
        *(float4*)&C[(size_t)(row0 + ty * 8 + r) * N + c0 + tx * 4] =
            make_float4(v0, v1, v2, v3);
    }
}

// ---------------- GAT aggregate (H=4, F=256): TWO warps per node ----------------
// half = warp&1 selects features [half*128, half*128+128); each warp needs only
// its own 2 heads' alphas, kept in registers and broadcast by shuffle.
__global__ void warp_agg4_kernel(const float* __restrict__ h, const int* __restrict__ nbr,
                                 const float* __restrict__ als, const float* __restrict__ ald,
                                 const float* __restrict__ bias, float* __restrict__ out) {
    int warp = threadIdx.x >> 5, lane = threadIdx.x & 31;
    int i = blockIdx.x * 4 + (warp >> 1);
    int half = warp & 1;

    int nbr_j = i;
    if (lane < 16) nbr_j = nbr[i * KNB + lane];

    // logits for this warp's two heads (head base = half*2)
    float2 sv = *(const float2*)&als[nbr_j * 4 + half * 2];
    float2 dv = *(const float2*)&ald[i * 4 + half * 2];
    float e0 = sv.x + dv.x, e1 = sv.y + dv.y;
    e0 = e0 > 0.f ? e0 : 0.2f * e0;
    e1 = e1 > 0.f ? e1 : 0.2f * e1;
    float m0 = lane < 17 ? e0 : -1e30f, m1 = lane < 17 ? e1 : -1e30f;
#pragma unroll
    for (int off = 16; off > 0; off >>= 1) {
        m0 = fmaxf(m0, __shfl_xor_sync(0xffffffffu, m0, off));
        m1 = fmaxf(m1, __shfl_xor_sync(0xffffffffu, m1, off));
    }
    float x0 = lane < 17 ? __expf(e0 - m0) : 0.f;
    float x1 = lane < 17 ? __expf(e1 - m1) : 0.f;
    float d0 = x0, d1 = x1;
#pragma unroll
    for (int off = 16; off > 0; off >>= 1) {
        d0 += __shfl_xor_sync(0xffffffffu, d0, off);
        d1 += __shfl_xor_sync(0xffffffffu, d1, off);
    }
    float al0 = x0 / d0;      // alpha for local head 0 (lanes' j)
    float al1 = x1 / d1;      // alpha for local head 1

    int fbase = half * 128 + lane * 4;
    float4 acc = make_float4(0.f, 0.f, 0.f, 0.f);
#pragma unroll
    for (int j = 0; j < 17; j++) {
        int g = __shfl_sync(0xffffffffu, nbr_j, j);
        float a0 = __shfl_sync(0xffffffffu, al0, j);
        float a1 = __shfl_sync(0xffffffffu, al1, j);
        float a = (lane < 16) ? a0 : a1;     // head = (lane*4)/64
        float4 v = *(const float4*)(h + g * 256 + fbase);
        acc.x += a * v.x; acc.y += a * v.y; acc.z += a * v.z; acc.w += a * v.w;
    }
    float4 bb = *(const float4*)&bias[fbase];
    float4 o = make_float4(geluf(acc.x + bb.x), geluf(acc.y + bb.y),
                           geluf(acc.z + bb.z), geluf(acc.w + bb.w));
    *(float4*)&out[i * 256 + fbase] = o;
}

// ---------------- GAT aggregate (H=1, F=128) + residual: TWO warps per node ------
__global__ void warp_agg1_kernel(const float* __restrict__ h, const int* __restrict__ nbr,
                                 const float* __restrict__ als, const float* __restrict__ ald,
                                 const float* __restrict__ bias, float* __restrict__ out,
                                 const float* __restrict__ x6, const float* __restrict__ resW,
                                 const float* __restrict__ resb) {
    int warp = threadIdx.x >> 5, lane = threadIdx.x & 31;
    int i = blockIdx.x * 4 + (warp >> 1);
    int half = warp & 1;

    int nbr_j = i;
    if (lane < 16) nbr_j = nbr[i * KNB + lane];

    float e = als[nbr_j] + ald[i];
    e = e > 0.f ? e : 0.2f * e;
    float m = lane < 17 ? e : -1e30f;
#pragma unroll
    for (int off = 16; off > 0; off >>= 1)
        m = fmaxf(m, __shfl_xor_sync(0xffffffffu, m, off));
    float xe = lane < 17 ? __expf(e - m) : 0.f;
    float den = xe;
#pragma unroll
    for (int off = 16; off > 0; off >>= 1)
        den += __shfl_xor_sync(0xffffffffu, den, off);
    float alpha = xe / den;

    int fbase = half * 64 + lane * 2;
    float2 acc = make_float2(0.f, 0.f);
#pragma unroll
    for (int j = 0; j < 17; j++) {
        int g = __shfl_sync(0xffffffffu, nbr_j, j);
        float a = __shfl_sync(0xffffffffu, alpha, j);
        float2 v = *(const float2*)(h + g * 128 + fbase);
        acc.x += a * v.x; acc.y += a * v.y;
    }
    float2 bb = *(const float2*)&bias[fbase];
    float2 o = make_float2(geluf(acc.x + bb.x), geluf(acc.y + bb.y));
    float2 r = *(const float2*)&resb[fbase];
#pragma unroll
    for (int d = 0; d < 6; d++) {
        float xv = x6[i * 6 + d];
        float2 w = *(const float2*)&resW[d * 128 + fbase];
        r.x += xv * w.x; r.y += xv * w.y;
    }
    o.x += r.x; o.y += r.y;
    *(float2*)&out[i * 128 + fbase] = o;
}

// ---------------- final ----------------
__global__ void final_kernel(const float* __restrict__ A, const float* __restrict__ W,
                             const float* __restrict__ b, float* __restrict__ out) {
    __shared__ float Ws[64 * 6];
    __shared__ float sb[6];
    int t = threadIdx.x;
    for (int k = t; k < 64 * 6; k += blockDim.x) Ws[k] = W[k];
    if (t < 6) sb[t] = b[t];
    __syncthreads();

    int i = blockIdx.x * blockDim.x + t;
    if (i >= NN) return;
    float acc[6];
#pragma unroll
    for (int o = 0; o < 6; o++) acc[o] = sb[o];
    const float4* Ar = (const float4*)(A + (size_t)i * 64);
#pragma unroll
    for (int k4 = 0; k4 < 16; k4++) {
        float4 v = Ar[k4];
        int k = k4 * 4;
#pragma unroll
        for (int o = 0; o < 6; o++) {
            acc[o] += v.x * Ws[(k + 0) * 6 + o];
            acc[o] += v.y * Ws[(k + 1) * 6 + o];
            acc[o] += v.z * Ws[(k + 2) * 6 + o];
            acc[o] += v.w * Ws[(k + 3) * 6 + o];
        }
    }
#pragma unroll
    for (int o = 0; o < 6; o++) out[(size_t)i * 6 + o] = acc[o];
}

// ---------------- launch ----------------
extern "C" void kernel_launch(void* const* d_in, const int* in_sizes, int n_in,
                              void* d_out, int out_size) {
    const float* x    = (const float*)d_in[0];
    const float* W1   = (const float*)d_in[1];
    const float* as1  = (const float*)d_in[2];
    const float* ad1  = (const float*)d_in[3];
    const float* b1   = (const float*)d_in[4];
    const float* W2   = (const float*)d_in[5];
    const float* as2  = (const float*)d_in[6];
    const float* ad2  = (const float*)d_in[7];
    const float* b2   = (const float*)d_in[8];
    const float* W3   = (const float*)d_in[9];
    const float* as3  = (const float*)d_in[10];
    const float* ad3  = (const float*)d_in[11];
    const float* b3   = (const float*)d_in[12];
    const float* resW = (const float*)d_in[13];
    const float* resb = (const float*)d_in[14];
    const float* m1W  = (const float*)d_in[15];
    const float* m1b  = (const float*)d_in[16];
    const float* m2W  = (const float*)d_in[17];
    const float* m2b  = (const float*)d_in[18];
    const float* m3W  = (const float*)d_in[19];
    const float* m3b  = (const float*)d_in[20];

    float *xp, *h, *a0, *a1, *als, *ald;
    int* nbr;
    cudaGetSymbolAddress((void**)&xp,  g_xp);
    cudaGetSymbolAddress((void**)&nbr, g_nbr);
    cudaGetSymbolAddress((void**)&h,   g_h);
    cudaGetSymbolAddress((void**)&a0,  g_act0);
    cudaGetSymbolAddress((void**)&a1,  g_act1);
    cudaGetSymbolAddress((void**)&als, g_als);
    cudaGetSymbolAddress((void**)&ald, g_ald);

    prep_kernel<<<NN / 256, 256>>>(x, xp);
    knn_kernel<<<NN / 16, 256>>>(xp, nbr);      // 2 queries per warp

    // GAT layer 1 (6 -> 256, H=4)
    gemm6_kernel<<<NN / 8, 256>>>(x, W1, as1, ad1, h, als, ald);
    warp_agg4_kernel<<<NN / 4, 256>>>(h, nbr, als, ald, b1, a0);

    // GAT layer 2 (256 -> 256, H=4): tf32 MMA + fused logits
    gemm_mma_kernel<<<dim3(NN / 128, 2), 256>>>(a0, W2, nullptr, h, 256, 256, 0,
                                                as2, ad2, als, ald, 4);
    warp_agg4_kernel<<<NN / 4, 256>>>(h, nbr, als, ald, b2, a1);

    // GAT layer 3 (256 -> 128, H=1) + fused residual
    gemm_mma_kernel<<<dim3(NN / 128, 1), 256>>>(a1, W3, nullptr, h, 256, 128, 0,
                                                as3, ad3, als, ald, 1);
    warp_agg1_kernel<<<NN / 4, 256>>>(h, nbr, als, ald, b3, a0, x, resW, resb);

    // MLP
    gemm_mma_kernel<<<dim3(NN / 128, 1), 256>>>(a0, m1W, m1b, a1, 128, 128, 1,
                                                nullptr, nullptr, nullptr, nullptr, 0);
    gemm_tile_kernel<<<dim3(NN / 128, 1), 256>>>(a1, m2W, m2b, h, 128, 64, 1);
    final_kernel<<<NN / 128, 128>>>(h, m3W, m3b, (float*)d_out);
}